// round 4
// baseline (speedup 1.0000x reference)
#include <cuda_runtime.h>
#include <cstdint>
#include <math.h>

#define DINLINE __device__ __forceinline__

constexpr int B_ = 256;
constexpr int C_ = 256;
constexpr int HW_ = 225;      // 15*15
constexpr int S_ = 8;
constexpr int NELEM = B_ * C_ * HW_;     // 14,745,600
constexpr int STATB = 4;                 // stat partial blocks (conv1x1 grid.y)
constexpr int UPD_BLOCKS = 15;           // update kernel grid.y

// ---------------- scratch (device globals; no allocation allowed) ----------
__device__ float g_concat[(size_t)B_ * 4 * C_ * HW_];  // 236 MB
__device__ float g_xc[NELEM];                          // 59 MB
__device__ float g_ybuf[NELEM];                        // 59 MB
__device__ float g_wft[4 * C_ * C_];
__device__ float g_w1t[C_ * C_];
__device__ float g_statsY[B_ * STATB * 2];
__device__ float g_stats2[B_ * UPD_BLOCKS * 2];

// ---------------- helpers --------------------------------------------------
DINLINE float elu_f(float v) { return v > 0.f ? v : expm1f(v); }

DINLINE uint32_t rotl32(uint32_t v, int s) { return __funnelshift_l(v, v, s); }

// packed f32x2 helpers
DINLINE unsigned long long pack2(float lo, float hi) {
    unsigned long long r;
    asm("mov.b64 %0, {%1, %2};" : "=l"(r) : "f"(lo), "f"(hi));
    return r;
}
DINLINE unsigned long long dup2(float v) {
    unsigned long long r;
    asm("mov.b64 %0, {%1, %1};" : "=l"(r) : "f"(v));
    return r;
}
DINLINE void unpack2(unsigned long long p, float& lo, float& hi) {
    asm("mov.b64 {%0, %1}, %2;" : "=f"(lo), "=f"(hi) : "l"(p));
}
DINLINE void fma2(unsigned long long& acc, unsigned long long x, unsigned long long w) {
    asm("fma.rn.f32x2 %0, %1, %2, %0;" : "+l"(acc) : "l"(x), "l"(w));
}

// Threefry-2x32, 20 rounds (JAX's threefry2x32 primitive)
DINLINE void threefry2x32(uint32_t k0, uint32_t k1, uint32_t& x0, uint32_t& x1) {
    uint32_t k2 = k0 ^ k1 ^ 0x1BD11BDAu;
    x0 += k0; x1 += k1;
#define TF_R(r) { x0 += x1; x1 = rotl32(x1, r); x1 ^= x0; }
    TF_R(13) TF_R(15) TF_R(26) TF_R(6)
    x0 += k1; x1 += k2 + 1u;
    TF_R(17) TF_R(29) TF_R(16) TF_R(24)
    x0 += k2; x1 += k0 + 2u;
    TF_R(13) TF_R(15) TF_R(26) TF_R(6)
    x0 += k0; x1 += k1 + 3u;
    TF_R(17) TF_R(29) TF_R(16) TF_R(24)
    x0 += k1; x1 += k2 + 4u;
    TF_R(13) TF_R(15) TF_R(26) TF_R(6)
    x0 += k2; x1 += k0 + 5u;
#undef TF_R
}

// ---------------- weight transpose ([CO][CI] -> [CI][CO]) ------------------
__global__ void transpose_kernel(const float* __restrict__ w, float* __restrict__ wt, int K) {
    int idx = blockIdx.x * 256 + threadIdx.x;
    if (idx < C_ * K) {
        int co = idx / K;
        int ci = idx % K;
        wt[ci * C_ + co] = w[idx];
    }
}

// ---------------- multi-tap direct conv + ELU -> concat buffer --------------
// block: one batch b, 64 output channels. 256 threads = 16 rows x 16 slots,
// each thread computes 4 contiguous output channels (cg*4+j) x 15 px of row r,
// accumulated as two packed f32x2 pairs per pixel.
template <int KH, int KW, int DIL, int PAD, int CIC>
__global__ void __launch_bounds__(256, 2)
conv_elu_kernel(const float* __restrict__ x,      // [B,256,15,15]
                const float* __restrict__ w,      // [256,256,KH,KW]
                const float* __restrict__ bias,   // [256]
                int co_off)                       // channel offset in concat
{
    constexpr int P = 15 + 2 * PAD;               // padded plane size
    constexpr int PST = (P + 3) & ~3;             // padded row stride (float4)
    constexpr int TAPS = KH * KW;
    constexpr int RW = 15 + (KW - 1) * DIL;       // row register width
    constexpr int RVV = (RW + 3) / 4;             // float4 loads per row
    constexpr int CPAD = 68;                      // co stride (pad vs bank conflict)

    __shared__ __align__(16) float sp[CIC][P][PST];
    __shared__ __align__(16) float sw[CIC][TAPS][CPAD];

    int b = blockIdx.x;
    int co_base = blockIdx.y * 64;
    int t = threadIdx.x;
    int r = t & 15;          // output row (0..14 active)
    int cg = t >> 4;         // 0..15 -> co quad base cg*4

    unsigned long long acc2[2][15];
    {
        float b0 = bias[co_base + cg * 4 + 0];
        float b1 = bias[co_base + cg * 4 + 1];
        float b2 = bias[co_base + cg * 4 + 2];
        float b3 = bias[co_base + cg * 4 + 3];
        unsigned long long p0 = pack2(b0, b1), p1 = pack2(b2, b3);
#pragma unroll
        for (int p = 0; p < 15; p++) { acc2[0][p] = p0; acc2[1][p] = p1; }
    }

    const float* xb = x + (size_t)b * C_ * HW_;

    for (int ci0 = 0; ci0 < C_; ci0 += CIC) {
        __syncthreads();
        // stage padded input patch for CIC channels
        constexpr int PATCH = CIC * P * PST;
        for (int idx = t; idx < PATCH; idx += 256) {
            int ci = idx / (P * PST);
            int rem = idx - ci * (P * PST);
            int py = rem / PST - PAD;
            int px = (rem % PST) - PAD;
            float v = 0.f;
            if (py >= 0 && py < 15 && px >= 0 && px < 15)
                v = xb[(ci0 + ci) * HW_ + py * 15 + px];
            ((float*)sp)[idx] = v;
        }
        // stage weights: sw[ci][tap][c] (co contiguous for packed reads)
        constexpr int WCNT = CIC * 64 * TAPS;
        for (int idx = t; idx < WCNT; idx += 256) {
            int c2 = idx / (CIC * TAPS);
            int rem = idx - c2 * (CIC * TAPS);
            int ci = rem / TAPS;
            int tap = rem - ci * TAPS;
            sw[ci][tap][c2] = w[((size_t)(co_base + c2) * C_ + (ci0 + ci)) * TAPS + tap];
        }
        __syncthreads();
        if (r < 15) {
#pragma unroll 1
            for (int ci = 0; ci < CIC; ci++) {
#pragma unroll 1
                for (int ky = 0; ky < KH; ky++) {
                    float rv[RVV * 4];
                    const float4* prow =
                        reinterpret_cast<const float4*>(&sp[ci][r + ky * DIL][0]);
#pragma unroll
                    for (int v = 0; v < RVV; v++) {
                        float4 q = prow[v];
                        rv[4 * v + 0] = q.x; rv[4 * v + 1] = q.y;
                        rv[4 * v + 2] = q.z; rv[4 * v + 3] = q.w;
                    }
#pragma unroll
                    for (int kx = 0; kx < KW; kx++) {
                        const ulonglong2 wq =
                            *reinterpret_cast<const ulonglong2*>(&sw[ci][ky * KW + kx][cg * 4]);
#pragma unroll
                        for (int px = 0; px < 15; px++) {
                            unsigned long long xx = dup2(rv[px + kx * DIL]);
                            fma2(acc2[0][px], xx, wq.x);
                            fma2(acc2[1][px], xx, wq.y);
                        }
                    }
                }
            }
        }
    }

    if (r < 15) {
#pragma unroll
        for (int j = 0; j < 2; j++) {
            float* o0 = g_concat + ((size_t)b * (4 * C_) + co_off + co_base + cg * 4 + 2 * j) * HW_ + r * 15;
            float* o1 = o0 + HW_;
#pragma unroll
            for (int px = 0; px < 15; px++) {
                float lo, hi;
                unpack2(acc2[j][px], lo, hi);
                o0[px] = elu_f(lo);
                o1[px] = elu_f(hi);
            }
        }
    }
}

// ---------------- 1x1 conv (per-batch GEMM), optional ELU / stats -----------
// block: one batch b, 64 output channels. 256 threads = 16 rows x 16 slots,
// 4 contiguous co per thread (cg*4+j), packed f32x2 accumulators.
template <int K, bool DO_ELU, bool DO_STATS>
__global__ void __launch_bounds__(256, 2)
conv1x1_kernel(const float* __restrict__ in,    // [B,K,225]
               const float* __restrict__ wt,    // [K,256] (ci-major)
               const float* __restrict__ bias,  // [256]
               float* __restrict__ out,         // [B,256,225]
               float* __restrict__ stats)       // [B][STATB][2] (pre-activation)
{
    __shared__ __align__(16) float sin_[16][15][16];
    __shared__ __align__(16) float sw[16][64];
    __shared__ float red[256];

    int b = blockIdx.x;
    int co_base = blockIdx.y * 64;
    int t = threadIdx.x;
    int r = t & 15;
    int cg = t >> 4;

    unsigned long long acc2[2][15];
    {
        float b0 = bias[co_base + cg * 4 + 0];
        float b1 = bias[co_base + cg * 4 + 1];
        float b2 = bias[co_base + cg * 4 + 2];
        float b3 = bias[co_base + cg * 4 + 3];
        unsigned long long p0 = pack2(b0, b1), p1 = pack2(b2, b3);
#pragma unroll
        for (int p = 0; p < 15; p++) { acc2[0][p] = p0; acc2[1][p] = p1; }
    }

    const float* inb = in + (size_t)b * K * HW_;

    for (int ci0 = 0; ci0 < K; ci0 += 16) {
        __syncthreads();
        for (int idx = t; idx < 16 * 225; idx += 256) {
            int ci = idx / 225;
            int p = idx - ci * 225;
            int row = p / 15;
            int px = p - row * 15;
            sin_[ci][row][px] = inb[(ci0 + ci) * HW_ + p];
        }
        for (int idx = t; idx < 16 * 64; idx += 256) {
            int ci = idx >> 6;
            int c = idx & 63;
            sw[ci][c] = wt[(size_t)(ci0 + ci) * C_ + co_base + c];
        }
        __syncthreads();
        if (r < 15) {
#pragma unroll 4
            for (int ci = 0; ci < 16; ci++) {
                float rv[16];
                const float4* prow = reinterpret_cast<const float4*>(&sin_[ci][r][0]);
#pragma unroll
                for (int v = 0; v < 4; v++) {
                    float4 q = prow[v];
                    rv[4 * v + 0] = q.x; rv[4 * v + 1] = q.y;
                    rv[4 * v + 2] = q.z; rv[4 * v + 3] = q.w;
                }
                const ulonglong2 wq =
                    *reinterpret_cast<const ulonglong2*>(&sw[ci][cg * 4]);
#pragma unroll
                for (int u = 0; u < 15; u++) {
                    unsigned long long xx = dup2(rv[u]);
                    fma2(acc2[0][u], xx, wq.x);
                    fma2(acc2[1][u], xx, wq.y);
                }
            }
        }
    }

    float s1 = 0.f, s2 = 0.f;
    if (r < 15) {
#pragma unroll
        for (int j = 0; j < 2; j++) {
            float* o0 = out + ((size_t)b * C_ + co_base + cg * 4 + 2 * j) * HW_ + r * 15;
            float* o1 = o0 + HW_;
#pragma unroll
            for (int u = 0; u < 15; u++) {
                float lo, hi;
                unpack2(acc2[j][u], lo, hi);
                if (DO_STATS) { s1 += lo + hi; s2 = fmaf(lo, lo, s2); s2 = fmaf(hi, hi, s2); }
                o0[u] = DO_ELU ? elu_f(lo) : lo;
                o1[u] = DO_ELU ? elu_f(hi) : hi;
            }
        }
    }
    if (DO_STATS) {
        __syncthreads();
        red[t] = s1; __syncthreads();
        for (int off = 128; off > 0; off >>= 1) {
            if (t < off) red[t] += red[t + off];
            __syncthreads();
        }
        if (t == 0) stats[((size_t)b * STATB + blockIdx.y) * 2 + 0] = red[0];
        __syncthreads();
        red[t] = s2; __syncthreads();
        for (int off = 128; off > 0; off >>= 1) {
            if (t < off) red[t] += red[t + off];
            __syncthreads();
        }
        if (t == 0) stats[((size_t)b * STATB + blockIdx.y) * 2 + 1] = red[0];
    }
}

// ---------------- per-step update: LN + ELU + noise + residual --------------
__global__ void __launch_bounds__(256)
step_update_kernel(const float* __restrict__ ybuf,
                   const float* __restrict__ lnw,
                   const float* __restrict__ lnb,
                   const float* __restrict__ xin,
                   float* __restrict__ xout,
                   const float* __restrict__ sp_arr,
                   const float* __restrict__ ss_arr,
                   const float* __restrict__ rw_arr,
                   const float* __restrict__ prob_arr,
                   int step)
{
    int b = blockIdx.x;
    int t = threadIdx.x;

    // LN stats over (C,H,W) for this batch (biased var, as jnp.var default)
    double sum = 0.0, sumsq = 0.0;
#pragma unroll
    for (int k = 0; k < STATB; k++) {
        sum   += (double)g_statsY[(b * STATB + k) * 2 + 0];
        sumsq += (double)g_statsY[(b * STATB + k) * 2 + 1];
    }
    const double n = (double)(C_ * HW_);
    double mu_d = sum / n;
    double var_d = sumsq / n - mu_d * mu_d;
    float mu = (float)mu_d;
    float rs = (float)(1.0 / sqrt(var_d + 1e-5));

    float sp = sp_arr[step];
    float ss = ss_arr[step];
    float rw = rw_arr[step];
    float prob = prob_arr[step];
    float cns = prob * ss;
    float rw1 = 1.f + rw;

    // fold_in(key(42), step) -> per-step key
    uint32_t fk0 = 0u, fk1 = (uint32_t)step;
    threefry2x32(0u, 42u, fk0, fk1);

    int q0 = blockIdx.y * 3840 + t;         // coalesced strided mapping
    size_t bbase = (size_t)b * (C_ * HW_);

    float s1 = 0.f, s2 = 0.f;
#pragma unroll
    for (int e = 0; e < 15; e++) {
        int q = q0 + e * 256;
        size_t gi = bbase + q;
        float y = ybuf[gi];
        float d = (y - mu) * rs;
        d = fmaf(d, lnw[q], lnb[q]);
        d = elu_f(d);
        s1 += d; s2 = fmaf(d, d, s2);
        // partitionable threefry random bits: counts64 hi=0, lo=flat index
        uint32_t c0 = 0u, c1 = (uint32_t)gi;
        threefry2x32(fk0, fk1, c0, c1);
        uint32_t bits = c0 ^ c1;
        float u = __uint_as_float(0x3f800000u | (bits >> 9)) - 1.0f;
        float xc = xin[gi];
        xout[gi] = fmaf(xc, rw1, fmaf(d, sp, u * cns));
    }

    __shared__ float red[256];
    red[t] = s1; __syncthreads();
    for (int off = 128; off > 0; off >>= 1) {
        if (t < off) red[t] += red[t + off];
        __syncthreads();
    }
    if (t == 0) g_stats2[(b * UPD_BLOCKS + blockIdx.y) * 2 + 0] = red[0];
    __syncthreads();
    red[t] = s2; __syncthreads();
    for (int off = 128; off > 0; off >>= 1) {
        if (t < off) red[t] += red[t + off];
        __syncthreads();
    }
    if (t == 0) g_stats2[(b * UPD_BLOCKS + blockIdx.y) * 2 + 1] = red[0];
}

// ---------------- finalize per-step unbiased variance -----------------------
__global__ void var_final_kernel(float* __restrict__ out_var, int step) {
    int b = threadIdx.x;  // 256 threads
    double s1 = 0.0, s2 = 0.0;
    for (int k = 0; k < UPD_BLOCKS; k++) {
        s1 += (double)g_stats2[(b * UPD_BLOCKS + k) * 2 + 0];
        s2 += (double)g_stats2[(b * UPD_BLOCKS + k) * 2 + 1];
    }
    const double n = (double)(C_ * HW_);
    double v = (s2 - s1 * s1 / n) / (n - 1.0);
    out_var[b * S_ + step] = (float)v;
}

// ---------------- launch ----------------------------------------------------
extern "C" void kernel_launch(void* const* d_in, const int* in_sizes, int n_in,
                              void* d_out, int out_size) {
    const float* x    = (const float*)d_in[0];
    const float* prob = (const float*)d_in[1];
    const float* w3   = (const float*)d_in[2];
    const float* b3   = (const float*)d_in[3];
    const float* w3d  = (const float*)d_in[4];
    const float* b3d  = (const float*)d_in[5];
    const float* w5   = (const float*)d_in[6];
    const float* b5   = (const float*)d_in[7];
    const float* w7   = (const float*)d_in[8];
    const float* b7   = (const float*)d_in[9];
    const float* wf   = (const float*)d_in[10];
    const float* bf   = (const float*)d_in[11];
    const float* w1   = (const float*)d_in[12];
    const float* b1   = (const float*)d_in[13];
    const float* lnw  = (const float*)d_in[14];
    const float* lnb  = (const float*)d_in[15];
    const float* spar = (const float*)d_in[16];
    const float* ssc  = (const float*)d_in[17];
    const float* rwv  = (const float*)d_in[18];

    float* out = (float*)d_out;
    float* out_var = out + (size_t)NELEM;

    float *concat, *xc, *ybuf, *wft, *w1t, *statsY;
    cudaGetSymbolAddress((void**)&concat, g_concat);
    cudaGetSymbolAddress((void**)&xc, g_xc);
    cudaGetSymbolAddress((void**)&ybuf, g_ybuf);
    cudaGetSymbolAddress((void**)&wft, g_wft);
    cudaGetSymbolAddress((void**)&w1t, g_w1t);
    cudaGetSymbolAddress((void**)&statsY, g_statsY);

    // transpose fusion + step weights to [ci][co]
    transpose_kernel<<<(C_ * 4 * C_ + 255) / 256, 256>>>(wf, wft, 4 * C_);
    transpose_kernel<<<(C_ * C_ + 255) / 256, 256>>>(w1, w1t, C_);

    // multi-scale perception -> g_concat
    dim3 gconv(B_, 4);
    conv_elu_kernel<3, 3, 1, 1, 8><<<gconv, 256>>>(x, w3, b3, 0);
    conv_elu_kernel<3, 3, 2, 2, 8><<<gconv, 256>>>(x, w3d, b3d, 256);
    conv_elu_kernel<5, 5, 1, 2, 4><<<gconv, 256>>>(x, w5, b5, 512);
    conv_elu_kernel<7, 7, 1, 3, 2><<<gconv, 256>>>(x, w7, b7, 768);

    // fusion 1x1 (4C -> C) + ELU -> g_xc
    conv1x1_kernel<1024, true, false><<<dim3(B_, STATB), 256>>>(concat, wft, bf, xc, nullptr);

    // 8 NCA steps
    for (int i = 0; i < S_; i++) {
        conv1x1_kernel<256, false, true><<<dim3(B_, STATB), 256>>>(xc, w1t, b1, ybuf, statsY);
        float* xo = (i == S_ - 1) ? out : xc;
        step_update_kernel<<<dim3(B_, UPD_BLOCKS), 256>>>(ybuf, lnw, lnb, xc, xo,
                                                          spar, ssc, rwv, prob, i);
        var_final_kernel<<<1, 256>>>(out_var, i);
    }
}

// round 7
// speedup vs baseline: 2.3502x; 2.3502x over previous
#include <cuda_runtime.h>
#include <cuda_bf16.h>
#include <cstdint>
#include <math.h>

#define DINLINE __device__ __forceinline__

constexpr int B_ = 256;
constexpr int C_ = 256;
constexpr int HW_ = 225;      // 15*15
constexpr int S_ = 8;
constexpr int NELEM = B_ * C_ * HW_;
constexpr int STATB = 4;
constexpr int UPD_BLOCKS = 15;

constexpr int PADP = 21;                     // padded plane 21x21 (pad=3)
constexpr int TAPS_TOTAL = 9 + 9 + 25 + 49;  // 92

// ---------------- scratch (device globals; no allocation allowed) ----------
__device__ float g_concat[(size_t)B_ * 4 * C_ * HW_];
__device__ float g_xc[NELEM];
__device__ float g_ybuf[NELEM];
__device__ float g_wft[4 * C_ * C_];
__device__ float g_w1t[C_ * C_];
__device__ float g_statsY[B_ * STATB * 2];
__device__ float g_stats2[B_ * UPD_BLOCKS * 2];
__device__ __nv_bfloat16 g_xph[(size_t)B_ * PADP * PADP * C_];
__device__ __nv_bfloat16 g_xpl[(size_t)B_ * PADP * PADP * C_];
__device__ __nv_bfloat16 g_wh[(size_t)TAPS_TOTAL * C_ * C_];
__device__ __nv_bfloat16 g_wl[(size_t)TAPS_TOTAL * C_ * C_];

// ---------------- helpers --------------------------------------------------
DINLINE float elu_f(float v) { return v > 0.f ? v : expm1f(v); }
DINLINE uint32_t rotl32(uint32_t v, int s) { return __funnelshift_l(v, v, s); }

DINLINE void threefry2x32(uint32_t k0, uint32_t k1, uint32_t& x0, uint32_t& x1) {
    uint32_t k2 = k0 ^ k1 ^ 0x1BD11BDAu;
    x0 += k0; x1 += k1;
#define TF_R(r) { x0 += x1; x1 = rotl32(x1, r); x1 ^= x0; }
    TF_R(13) TF_R(15) TF_R(26) TF_R(6)
    x0 += k1; x1 += k2 + 1u;
    TF_R(17) TF_R(29) TF_R(16) TF_R(24)
    x0 += k2; x1 += k0 + 2u;
    TF_R(13) TF_R(15) TF_R(26) TF_R(6)
    x0 += k0; x1 += k1 + 3u;
    TF_R(17) TF_R(29) TF_R(16) TF_R(24)
    x0 += k1; x1 += k2 + 4u;
    TF_R(13) TF_R(15) TF_R(26) TF_R(6)
    x0 += k2; x1 += k0 + 5u;
#undef TF_R
}

DINLINE uint32_t smem_to_u32(const void* p) {
    uint32_t a;
    asm("{ .reg .u64 t; cvta.to.shared.u64 t, %1; cvt.u32.u64 %0, t; }"
        : "=r"(a) : "l"(p));
    return a;
}

// legacy HMMA path: baseline PTX ISA, valid on plain sm_103
DINLINE void ldm_x4(uint32_t* r, uint32_t addr) {
    asm volatile("ldmatrix.sync.aligned.m8n8.x4.shared.b16 {%0,%1,%2,%3}, [%4];"
                 : "=r"(r[0]), "=r"(r[1]), "=r"(r[2]), "=r"(r[3]) : "r"(addr));
}
DINLINE void mma_bf16(float* c, const uint32_t* a, const uint32_t* b) {
    asm volatile(
        "mma.sync.aligned.m16n8k16.row.col.f32.bf16.bf16.f32 "
        "{%0,%1,%2,%3}, {%4,%5,%6,%7}, {%8,%9}, {%0,%1,%2,%3};"
        : "+f"(c[0]), "+f"(c[1]), "+f"(c[2]), "+f"(c[3])
        : "r"(a[0]), "r"(a[1]), "r"(a[2]), "r"(a[3]), "r"(b[0]), "r"(b[1]));
}

// ---------------- prep: pad + bf16 split of x (channels-last) ---------------
__global__ void pad_split_kernel(const float* __restrict__ x) {
    int c = threadIdx.x;
    int b = blockIdx.x;
    int pp = blockIdx.y;                   // 0..440
    int py = pp / PADP, px = pp - py * PADP;
    float v = 0.f;
    int iy = py - 3, ix = px - 3;
    if (iy >= 0 && iy < 15 && ix >= 0 && ix < 15)
        v = x[((size_t)b * C_ + c) * HW_ + iy * 15 + ix];
    __nv_bfloat16 h = __float2bfloat16(v);
    float r = v - __bfloat162float(h);
    size_t o = ((size_t)b * (PADP * PADP) + pp) * C_ + c;
    g_xph[o] = h;
    g_xpl[o] = __float2bfloat16(r);
}

// ---------------- prep: split conv weights -> [tap][co][ci] -----------------
__global__ void wsplit_kernel(const float* __restrict__ w, int taps, int tap_off) {
    int idx = blockIdx.x * 256 + threadIdx.x;
    int total = C_ * C_ * taps;
    if (idx >= total) return;
    int tap = idx % taps;
    int rest = idx / taps;
    int ci = rest & 255;
    int co = rest >> 8;
    float v = w[idx];
    __nv_bfloat16 h = __float2bfloat16(v);
    float r = v - __bfloat162float(h);
    size_t o = ((size_t)(tap_off + tap) * C_ + co) * C_ + ci;
    g_wh[o] = h;
    g_wl[o] = __float2bfloat16(r);
}

// ---------------- HMMA implicit-GEMM conv + bias + ELU ----------------------
// CTA: 128 pixels x 128 co; 8 warps (2x4), warp tile 64x32.
// Split-bf16: acc += Ah*Bh + Ah*Bl + Al*Bh (fp32 accum; lo*lo dropped).
template <int KH, int KW, int DIL, int PAD>
__global__ void __launch_bounds__(256, 2)
conv_hmma_kernel(const __nv_bfloat16* __restrict__ xph,
                 const __nv_bfloat16* __restrict__ xpl,
                 const __nv_bfloat16* __restrict__ wh,   // [tap][co][ci]
                 const __nv_bfloat16* __restrict__ wl,
                 const float* __restrict__ bias,
                 int co_off)
{
    constexpr int TAPS = KH * KW;
    constexpr int RSTR = 24;   // smem row stride in bf16 (48B, conflict-free ldmatrix)

    __shared__ __align__(16) __nv_bfloat16 sAh[128][RSTR];
    __shared__ __align__(16) __nv_bfloat16 sAl[128][RSTR];
    __shared__ __align__(16) __nv_bfloat16 sBh[128][RSTR];
    __shared__ __align__(16) __nv_bfloat16 sBl[128][RSTR];

    int t = threadIdx.x;
    int lane = t & 31;
    int wid = t >> 5;
    int wm = wid >> 2;          // 0..1  (m 64-tile)
    int wn = wid & 3;           // 0..3  (n 32-tile)

    // staging mapping: 2 threads per row
    int row = t >> 1, half = t & 1;
    int gp = blockIdx.x * 128 + row;
    int b = gp / 225;
    int rem = gp - b * 225;
    int y = rem / 15, xx = rem - y * 15;
    const int OFF = 3 - PAD;
    int coBase = blockIdx.y * 128;
    int bco = coBase + row;

    // ldmatrix lane address components
    int ag = lane >> 3, alr = lane & 7;
    int a_row = (ag & 1) * 8 + alr;      // + m0
    int a_kb  = (ag >> 1) * 16;          // k byte offset
    int b_row = (ag >> 1) * 8 + alr;     // + n0
    int b_kb  = (ag & 1) * 16;

    uint32_t sAh_b = smem_to_u32(sAh), sAl_b = smem_to_u32(sAl);
    uint32_t sBh_b = smem_to_u32(sBh), sBl_b = smem_to_u32(sBl);

    float acc[4][4][4];
#pragma unroll
    for (int i = 0; i < 4; i++)
#pragma unroll
        for (int j = 0; j < 4; j++)
#pragma unroll
            for (int k = 0; k < 4; k++) acc[i][j][k] = 0.f;

#pragma unroll 1
    for (int tap = 0; tap < TAPS; tap++) {
        int ky = tap / KW, kx = tap - (tap / KW) * KW;
        int sy = y + ky * DIL + OFF;
        int sx = xx + kx * DIL + OFF;
        size_t abase = (((size_t)b * PADP + sy) * PADP + sx) * C_;
        size_t bbase = ((size_t)tap * C_ + bco) * C_;
#pragma unroll 1
        for (int c16 = 0; c16 < 16; c16++) {
            __syncthreads();
            int ci0 = c16 * 16 + half * 8;
            *reinterpret_cast<uint4*>(&sAh[row][half * 8]) =
                *reinterpret_cast<const uint4*>(xph + abase + ci0);
            *reinterpret_cast<uint4*>(&sAl[row][half * 8]) =
                *reinterpret_cast<const uint4*>(xpl + abase + ci0);
            *reinterpret_cast<uint4*>(&sBh[row][half * 8]) =
                *reinterpret_cast<const uint4*>(wh + bbase + ci0);
            *reinterpret_cast<uint4*>(&sBl[row][half * 8]) =
                *reinterpret_cast<const uint4*>(wl + bbase + ci0);
            __syncthreads();

            // B fragments for this warp's 32 co: 2x ldmatrix.x4 each (hi, lo)
            uint32_t bh[8], bl[8];
#pragma unroll
            for (int h = 0; h < 2; h++) {
                int n0 = wn * 32 + h * 16;
                ldm_x4(&bh[h * 4], sBh_b + (uint32_t)((n0 + b_row) * (RSTR * 2)) + b_kb);
                ldm_x4(&bl[h * 4], sBl_b + (uint32_t)((n0 + b_row) * (RSTR * 2)) + b_kb);
            }
#pragma unroll
            for (int mt = 0; mt < 4; mt++) {
                int m0 = wm * 64 + mt * 16;
                uint32_t af[4];
                ldm_x4(af, sAh_b + (uint32_t)((m0 + a_row) * (RSTR * 2)) + a_kb);
#pragma unroll
                for (int nt = 0; nt < 4; nt++) {
                    const uint32_t* bp = &bh[(nt >> 1) * 4 + (nt & 1) * 2];
                    mma_bf16(acc[mt][nt], af, bp);
                    const uint32_t* bq = &bl[(nt >> 1) * 4 + (nt & 1) * 2];
                    mma_bf16(acc[mt][nt], af, bq);
                }
                ldm_x4(af, sAl_b + (uint32_t)((m0 + a_row) * (RSTR * 2)) + a_kb);
#pragma unroll
                for (int nt = 0; nt < 4; nt++) {
                    const uint32_t* bp = &bh[(nt >> 1) * 4 + (nt & 1) * 2];
                    mma_bf16(acc[mt][nt], af, bp);
                }
            }
        }
    }

    // epilogue: bias + ELU + store to concat [b][co][p]
#pragma unroll
    for (int mt = 0; mt < 4; mt++) {
#pragma unroll
        for (int nt = 0; nt < 4; nt++) {
            int co = coBase + wn * 32 + nt * 8 + (lane & 3) * 2;
            float bv0 = bias[co], bv1 = bias[co + 1];
#pragma unroll
            for (int rr = 0; rr < 2; rr++) {
                int pr = blockIdx.x * 128 + wm * 64 + mt * 16 + (lane >> 2) + rr * 8;
                int pb = pr / 225;
                int pp = pr - pb * 225;
                float* o = g_concat + ((size_t)pb * (4 * C_) + co_off + co) * HW_ + pp;
                float v0 = acc[mt][nt][rr * 2 + 0] + bv0;
                float v1 = acc[mt][nt][rr * 2 + 1] + bv1;
                o[0] = elu_f(v0);
                o[HW_] = elu_f(v1);
            }
        }
    }
}

// ---------------- weight transpose ([CO][CI] -> [CI][CO]) ------------------
__global__ void transpose_kernel(const float* __restrict__ w, float* __restrict__ wt, int K) {
    int idx = blockIdx.x * 256 + threadIdx.x;
    if (idx < C_ * K) {
        int co = idx / K;
        int ci = idx % K;
        wt[ci * C_ + co] = w[idx];
    }
}

// ---------------- 1x1 conv (per-batch GEMM, scalar fp32) --------------------
template <int K, bool DO_ELU, bool DO_STATS>
__global__ void __launch_bounds__(256, 2)
conv1x1_kernel(const float* __restrict__ in,
               const float* __restrict__ wt,
               const float* __restrict__ bias,
               float* __restrict__ out,
               float* __restrict__ stats)
{
    __shared__ __align__(16) float sin_[16][15][16];
    __shared__ __align__(16) float sw[16][64];
    __shared__ float red[256];

    int b = blockIdx.x;
    int co_base = blockIdx.y * 64;
    int t = threadIdx.x;
    int r = t & 15;
    int cg = t >> 4;

    float acc[4][15];
#pragma unroll
    for (int j = 0; j < 4; j++) {
        float bv = bias[co_base + cg * 4 + j];
#pragma unroll
        for (int p = 0; p < 15; p++) acc[j][p] = bv;
    }

    const float* inb = in + (size_t)b * K * HW_;

    for (int ci0 = 0; ci0 < K; ci0 += 16) {
        __syncthreads();
        for (int idx = t; idx < 16 * 225; idx += 256) {
            int ci = idx / 225;
            int p = idx - ci * 225;
            int row = p / 15;
            int px = p - row * 15;
            sin_[ci][row][px] = inb[(ci0 + ci) * HW_ + p];
        }
        for (int idx = t; idx < 16 * 64; idx += 256) {
            int ci = idx >> 6;
            int c = idx & 63;
            sw[ci][c] = wt[(size_t)(ci0 + ci) * C_ + co_base + c];
        }
        __syncthreads();
        if (r < 15) {
#pragma unroll 4
            for (int ci = 0; ci < 16; ci++) {
                float rv[16];
                const float4* prow = reinterpret_cast<const float4*>(&sin_[ci][r][0]);
#pragma unroll
                for (int v = 0; v < 4; v++) {
                    float4 q = prow[v];
                    rv[4 * v + 0] = q.x; rv[4 * v + 1] = q.y;
                    rv[4 * v + 2] = q.z; rv[4 * v + 3] = q.w;
                }
                float4 wq = *reinterpret_cast<const float4*>(&sw[ci][cg * 4]);
#pragma unroll
                for (int u = 0; u < 15; u++) {
                    float xv = rv[u];
                    acc[0][u] = fmaf(xv, wq.x, acc[0][u]);
                    acc[1][u] = fmaf(xv, wq.y, acc[1][u]);
                    acc[2][u] = fmaf(xv, wq.z, acc[2][u]);
                    acc[3][u] = fmaf(xv, wq.w, acc[3][u]);
                }
            }
        }
    }

    float s1 = 0.f, s2 = 0.f;
    if (r < 15) {
#pragma unroll
        for (int j = 0; j < 4; j++) {
            int co = co_base + cg * 4 + j;
            float* o = out + ((size_t)b * C_ + co) * HW_ + r * 15;
#pragma unroll
            for (int u = 0; u < 15; u++) {
                float v = acc[j][u];
                if (DO_STATS) { s1 += v; s2 = fmaf(v, v, s2); }
                o[u] = DO_ELU ? elu_f(v) : v;
            }
        }
    }
    if (DO_STATS) {
        __syncthreads();
        red[t] = s1; __syncthreads();
        for (int off = 128; off > 0; off >>= 1) {
            if (t < off) red[t] += red[t + off];
            __syncthreads();
        }
        if (t == 0) stats[((size_t)b * STATB + blockIdx.y) * 2 + 0] = red[0];
        __syncthreads();
        red[t] = s2; __syncthreads();
        for (int off = 128; off > 0; off >>= 1) {
            if (t < off) red[t] += red[t + off];
            __syncthreads();
        }
        if (t == 0) stats[((size_t)b * STATB + blockIdx.y) * 2 + 1] = red[0];
    }
}

// ---------------- per-step update: LN + ELU + noise + residual --------------
__global__ void __launch_bounds__(256)
step_update_kernel(const float* __restrict__ ybuf,
                   const float* __restrict__ lnw,
                   const float* __restrict__ lnb,
                   const float* __restrict__ xin,
                   float* __restrict__ xout,
                   const float* __restrict__ sp_arr,
                   const float* __restrict__ ss_arr,
                   const float* __restrict__ rw_arr,
                   const float* __restrict__ prob_arr,
                   int step)
{
    int b = blockIdx.x;
    int t = threadIdx.x;

    double sum = 0.0, sumsq = 0.0;
#pragma unroll
    for (int k = 0; k < STATB; k++) {
        sum   += (double)g_statsY[(b * STATB + k) * 2 + 0];
        sumsq += (double)g_statsY[(b * STATB + k) * 2 + 1];
    }
    const double n = (double)(C_ * HW_);
    double mu_d = sum / n;
    double var_d = sumsq / n - mu_d * mu_d;
    float mu = (float)mu_d;
    float rs = (float)(1.0 / sqrt(var_d + 1e-5));

    float sp = sp_arr[step];
    float ss = ss_arr[step];
    float rw = rw_arr[step];
    float prob = prob_arr[step];
    float cns = prob * ss;
    float rw1 = 1.f + rw;

    uint32_t fk0 = 0u, fk1 = (uint32_t)step;
    threefry2x32(0u, 42u, fk0, fk1);

    int q0 = blockIdx.y * 3840 + t;
    size_t bbase = (size_t)b * (C_ * HW_);

    float s1 = 0.f, s2 = 0.f;
#pragma unroll
    for (int e = 0; e < 15; e++) {
        int q = q0 + e * 256;
        size_t gi = bbase + q;
        float y = ybuf[gi];
        float d = (y - mu) * rs;
        d = fmaf(d, lnw[q], lnb[q]);
        d = elu_f(d);
        s1 += d; s2 = fmaf(d, d, s2);
        uint32_t c0 = 0u, c1 = (uint32_t)gi;
        threefry2x32(fk0, fk1, c0, c1);
        uint32_t bits = c0 ^ c1;
        float u = __uint_as_float(0x3f800000u | (bits >> 9)) - 1.0f;
        float xc = xin[gi];
        xout[gi] = fmaf(xc, rw1, fmaf(d, sp, u * cns));
    }

    __shared__ float red[256];
    red[t] = s1; __syncthreads();
    for (int off = 128; off > 0; off >>= 1) {
        if (t < off) red[t] += red[t + off];
        __syncthreads();
    }
    if (t == 0) g_stats2[(b * UPD_BLOCKS + blockIdx.y) * 2 + 0] = red[0];
    __syncthreads();
    red[t] = s2; __syncthreads();
    for (int off = 128; off > 0; off >>= 1) {
        if (t < off) red[t] += red[t + off];
        __syncthreads();
    }
    if (t == 0) g_stats2[(b * UPD_BLOCKS + blockIdx.y) * 2 + 1] = red[0];
}

// ---------------- finalize per-step unbiased variance -----------------------
__global__ void var_final_kernel(float* __restrict__ out_var, int step) {
    int b = threadIdx.x;
    double s1 = 0.0, s2 = 0.0;
    for (int k = 0; k < UPD_BLOCKS; k++) {
        s1 += (double)g_stats2[(b * UPD_BLOCKS + k) * 2 + 0];
        s2 += (double)g_stats2[(b * UPD_BLOCKS + k) * 2 + 1];
    }
    const double n = (double)(C_ * HW_);
    double v = (s2 - s1 * s1 / n) / (n - 1.0);
    out_var[b * S_ + step] = (float)v;
}

// ---------------- launch ----------------------------------------------------
extern "C" void kernel_launch(void* const* d_in, const int* in_sizes, int n_in,
                              void* d_out, int out_size) {
    const float* x    = (const float*)d_in[0];
    const float* prob = (const float*)d_in[1];
    const float* w3   = (const float*)d_in[2];
    const float* b3   = (const float*)d_in[3];
    const float* w3d  = (const float*)d_in[4];
    const float* b3d  = (const float*)d_in[5];
    const float* w5   = (const float*)d_in[6];
    const float* b5   = (const float*)d_in[7];
    const float* w7   = (const float*)d_in[8];
    const float* b7   = (const float*)d_in[9];
    const float* wf   = (const float*)d_in[10];
    const float* bf   = (const float*)d_in[11];
    const float* w1   = (const float*)d_in[12];
    const float* b1   = (const float*)d_in[13];
    const float* lnw  = (const float*)d_in[14];
    const float* lnb  = (const float*)d_in[15];
    const float* spar = (const float*)d_in[16];
    const float* ssc  = (const float*)d_in[17];
    const float* rwv  = (const float*)d_in[18];

    float* out = (float*)d_out;
    float* out_var = out + (size_t)NELEM;

    float *concat, *xc, *ybuf, *wft, *w1t, *statsY;
    __nv_bfloat16 *xph, *xpl, *wh, *wl;
    cudaGetSymbolAddress((void**)&concat, g_concat);
    cudaGetSymbolAddress((void**)&xc, g_xc);
    cudaGetSymbolAddress((void**)&ybuf, g_ybuf);
    cudaGetSymbolAddress((void**)&wft, g_wft);
    cudaGetSymbolAddress((void**)&w1t, g_w1t);
    cudaGetSymbolAddress((void**)&statsY, g_statsY);
    cudaGetSymbolAddress((void**)&xph, g_xph);
    cudaGetSymbolAddress((void**)&xpl, g_xpl);
    cudaGetSymbolAddress((void**)&wh, g_wh);
    cudaGetSymbolAddress((void**)&wl, g_wl);

    // prep: pad+split image, split conv weights, transpose 1x1 weights
    pad_split_kernel<<<dim3(B_, PADP * PADP), 256>>>(x);
    wsplit_kernel<<<(C_ * C_ * 9 + 255) / 256, 256>>>(w3, 9, 0);
    wsplit_kernel<<<(C_ * C_ * 9 + 255) / 256, 256>>>(w3d, 9, 9);
    wsplit_kernel<<<(C_ * C_ * 25 + 255) / 256, 256>>>(w5, 25, 18);
    wsplit_kernel<<<(C_ * C_ * 49 + 255) / 256, 256>>>(w7, 49, 43);
    transpose_kernel<<<(C_ * 4 * C_ + 255) / 256, 256>>>(wf, wft, 4 * C_);
    transpose_kernel<<<(C_ * C_ + 255) / 256, 256>>>(w1, w1t, C_);

    // multi-scale perception -> g_concat (HMMA tensor cores)
    dim3 gconv(450, 2);
    conv_hmma_kernel<3, 3, 1, 1><<<gconv, 256>>>(
        xph, xpl, wh + (size_t)0 * C_ * C_, wl + (size_t)0 * C_ * C_, b3, 0);
    conv_hmma_kernel<3, 3, 2, 2><<<gconv, 256>>>(
        xph, xpl, wh + (size_t)9 * C_ * C_, wl + (size_t)9 * C_ * C_, b3d, 256);
    conv_hmma_kernel<5, 5, 1, 2><<<gconv, 256>>>(
        xph, xpl, wh + (size_t)18 * C_ * C_, wl + (size_t)18 * C_ * C_, b5, 512);
    conv_hmma_kernel<7, 7, 1, 3><<<gconv, 256>>>(
        xph, xpl, wh + (size_t)43 * C_ * C_, wl + (size_t)43 * C_ * C_, b7, 768);

    // fusion 1x1 (4C -> C) + ELU -> g_xc
    conv1x1_kernel<1024, true, false><<<dim3(B_, STATB), 256>>>(concat, wft, bf, xc, nullptr);

    // 8 NCA steps
    for (int i = 0; i < S_; i++) {
        conv1x1_kernel<256, false, true><<<dim3(B_, STATB), 256>>>(xc, w1t, b1, ybuf, statsY);
        float* xo = (i == S_ - 1) ? out : xc;
        step_update_kernel<<<dim3(B_, UPD_BLOCKS), 256>>>(ybuf, lnw, lnb, xc, xo,
                                                          spar, ssc, rwv, prob, i);
        var_final_kernel<<<1, 256>>>(out_var, i);
    }
}

// round 9
// speedup vs baseline: 4.2168x; 1.7943x over previous
#include <cuda_runtime.h>
#include <cuda_bf16.h>
#include <cstdint>
#include <math.h>

#define DINLINE __device__ __forceinline__

constexpr int B_ = 256;
constexpr int C_ = 256;
constexpr int HW_ = 225;
constexpr int S_ = 8;
constexpr int NELEM = B_ * C_ * HW_;      // 14,745,600
constexpr int NPIX = B_ * HW_;            // 57600
constexpr int UPD_BLOCKS = 15;
constexpr int PADP = 21;
constexpr int TAPS_TOTAL = 92;

// ---------------- scratch ---------------------------------------------------
__device__ __nv_bfloat16 g_xph[(size_t)B_ * PADP * PADP * C_];
__device__ __nv_bfloat16 g_xpl[(size_t)B_ * PADP * PADP * C_];
__device__ __nv_bfloat16 g_wh[(size_t)TAPS_TOTAL * C_ * C_];
__device__ __nv_bfloat16 g_wl[(size_t)TAPS_TOTAL * C_ * C_];
__device__ __nv_bfloat16 g_wfh[4 * C_ * C_];
__device__ __nv_bfloat16 g_wfl[4 * C_ * C_];
__device__ __nv_bfloat16 g_w1h[C_ * C_];
__device__ __nv_bfloat16 g_w1l[C_ * C_];
__device__ __nv_bfloat16 g_cath[(size_t)NPIX * 1024];   // channels-last concat hi
__device__ __nv_bfloat16 g_catl[(size_t)NPIX * 1024];
__device__ float g_xc[NELEM];                            // channels-last [b][p][c]
__device__ __nv_bfloat16 g_xch[NELEM];
__device__ __nv_bfloat16 g_xcl[NELEM];
__device__ float g_ybuf[NELEM];                          // channels-last
__device__ float g_nz[(size_t)S_ * NELEM];               // noise, channels-last
__device__ float g_lnwt[C_ * HW_];                       // [p][c]
__device__ float g_lnbt[C_ * HW_];
__device__ float g_statsY[B_ * 2];
__device__ float g_stats2[B_ * UPD_BLOCKS * 2];

// ---------------- helpers ---------------------------------------------------
DINLINE float elu_f(float v) { return v > 0.f ? v : expm1f(v); }
DINLINE uint32_t rotl32(uint32_t v, int s) { return __funnelshift_l(v, v, s); }

DINLINE void threefry2x32(uint32_t k0, uint32_t k1, uint32_t& x0, uint32_t& x1) {
    uint32_t k2 = k0 ^ k1 ^ 0x1BD11BDAu;
    x0 += k0; x1 += k1;
#define TF_R(r) { x0 += x1; x1 = rotl32(x1, r); x1 ^= x0; }
    TF_R(13) TF_R(15) TF_R(26) TF_R(6)
    x0 += k1; x1 += k2 + 1u;
    TF_R(17) TF_R(29) TF_R(16) TF_R(24)
    x0 += k2; x1 += k0 + 2u;
    TF_R(13) TF_R(15) TF_R(26) TF_R(6)
    x0 += k0; x1 += k1 + 3u;
    TF_R(17) TF_R(29) TF_R(16) TF_R(24)
    x0 += k1; x1 += k2 + 4u;
    TF_R(13) TF_R(15) TF_R(26) TF_R(6)
    x0 += k2; x1 += k0 + 5u;
#undef TF_R
}

DINLINE uint32_t smem_to_u32(const void* p) {
    uint32_t a;
    asm("{ .reg .u64 t; cvta.to.shared.u64 t, %1; cvt.u32.u64 %0, t; }"
        : "=r"(a) : "l"(p));
    return a;
}
DINLINE void ldm_x4(uint32_t* r, uint32_t addr) {
    asm volatile("ldmatrix.sync.aligned.m8n8.x4.shared.b16 {%0,%1,%2,%3}, [%4];"
                 : "=r"(r[0]), "=r"(r[1]), "=r"(r[2]), "=r"(r[3]) : "r"(addr));
}
DINLINE void mma_bf16(float* c, const uint32_t* a, const uint32_t* b) {
    asm volatile(
        "mma.sync.aligned.m16n8k16.row.col.f32.bf16.bf16.f32 "
        "{%0,%1,%2,%3}, {%4,%5,%6,%7}, {%8,%9}, {%0,%1,%2,%3};"
        : "+f"(c[0]), "+f"(c[1]), "+f"(c[2]), "+f"(c[3])
        : "r"(a[0]), "r"(a[1]), "r"(a[2]), "r"(a[3]), "r"(b[0]), "r"(b[1]));
}
DINLINE void cp16(uint32_t dst, const void* src) {
    asm volatile("cp.async.cg.shared.global [%0], [%1], 16;" :: "r"(dst), "l"(src));
}
DINLINE void cp_commit() { asm volatile("cp.async.commit_group;"); }
template <int N> DINLINE void cp_wait() { asm volatile("cp.async.wait_group %0;" :: "n"(N)); }

DINLINE void split_bf16(float v, __nv_bfloat16& h, __nv_bfloat16& l) {
    h = __float2bfloat16(v);
    l = __float2bfloat16(v - __bfloat162float(h));
}

// ---------------- prep kernels ----------------------------------------------
__global__ void pad_split_kernel(const float* __restrict__ x) {
    int c = threadIdx.x;
    int b = blockIdx.x;
    int pp = blockIdx.y;
    int py = pp / PADP, px = pp - py * PADP;
    float v = 0.f;
    int iy = py - 3, ix = px - 3;
    if (iy >= 0 && iy < 15 && ix >= 0 && ix < 15)
        v = x[((size_t)b * C_ + c) * HW_ + iy * 15 + ix];
    __nv_bfloat16 h, l;
    split_bf16(v, h, l);
    size_t o = ((size_t)b * (PADP * PADP) + pp) * C_ + c;
    g_xph[o] = h;
    g_xpl[o] = l;
}

__global__ void wsplit_kernel(const float* __restrict__ w, int taps, int tap_off) {
    int idx = blockIdx.x * 256 + threadIdx.x;
    if (idx >= C_ * C_ * taps) return;
    int tap = idx % taps;
    int rest = idx / taps;
    int ci = rest & 255;
    int co = rest >> 8;
    __nv_bfloat16 h, l;
    split_bf16(w[idx], h, l);
    size_t o = ((size_t)(tap_off + tap) * C_ + co) * C_ + ci;
    g_wh[o] = h;
    g_wl[o] = l;
}

__global__ void wsplit1_kernel(const float* __restrict__ w,
                               __nv_bfloat16* __restrict__ h,
                               __nv_bfloat16* __restrict__ l, int n) {
    int idx = blockIdx.x * 256 + threadIdx.x;
    if (idx >= n) return;
    split_bf16(w[idx], h[idx], l[idx]);
}

__global__ void lnT_kernel(const float* __restrict__ lnw, const float* __restrict__ lnb) {
    int p = blockIdx.x, c = threadIdx.x;
    g_lnwt[p * 256 + c] = lnw[c * 225 + p];
    g_lnbt[p * 256 + c] = lnb[c * 225 + p];
}

// ---------------- noise pre-generation (stream 2) ---------------------------
__global__ void __launch_bounds__(256)
noise_kernel(int step) {
    int b = blockIdx.x, yb = blockIdx.y, t = threadIdx.x;
    uint32_t fk0 = 0u, fk1 = (uint32_t)step;
    threefry2x32(0u, 42u, fk0, fk1);
    float* o = g_nz + (size_t)step * NELEM + (size_t)b * 57600;
#pragma unroll
    for (int e = 0; e < 15; e++) {
        int p = yb * 15 + e;
        uint32_t c0 = 0u, c1 = (uint32_t)((b * 256 + t) * 225 + p);
        threefry2x32(fk0, fk1, c0, c1);
        uint32_t bits = c0 ^ c1;
        o[p * 256 + t] = __uint_as_float(0x3f800000u | (bits >> 9)) - 1.0f;
    }
}

// ---------------- unified HMMA kernel ---------------------------------------
// CTA: 128 M-rows (pixels) x 128 N-cols (channels); 8 warps 2x4, warp 64x32.
// K-chunks of 32, cp.async double-buffered. Split-bf16: Ah*Bh + Ah*Bl + Al*Bh.
constexpr int EPI_CONV = 0, EPI_FUSION = 1, EPI_STEP = 2;
constexpr int RSTR = 40;                    // bf16/row (80B): 16B-aligned, conflict-free
constexpr int ARRB = 128 * RSTR * 2;        // bytes per array (10240)
constexpr int HMMA_SMEM = 2 * 4 * ARRB;     // 81920

template <int KH, int KW, int DIL, int PAD, int KDIM, int EPI, bool GATHER>
__global__ void __launch_bounds__(256, 2)
hmma_kernel(const __nv_bfloat16* __restrict__ ah, const __nv_bfloat16* __restrict__ al,
            const __nv_bfloat16* __restrict__ bh, const __nv_bfloat16* __restrict__ bl,
            const float* __restrict__ bias,
            __nv_bfloat16* __restrict__ oh, __nv_bfloat16* __restrict__ ol,
            float* __restrict__ of, int co_off)
{
    constexpr int TAPS = KH * KW;
    constexpr int NCH = GATHER ? TAPS * 8 : KDIM / 32;
    extern __shared__ __align__(16) char sm[];
    uint32_t smb = smem_to_u32(sm);

    int t = threadIdx.x, lane = t & 31, wid = t >> 5;
    int wm = wid >> 2, wn = wid & 3;
    int row = t >> 1, q0 = (t & 1) * 2;
    int gp = blockIdx.x * 128 + row;
    int b = gp / 225, rem = gp - b * 225, y = rem / 15, xx = rem - y * 15;
    int coBase = blockIdx.y * 128;
    int bco = coBase + row;
    const int OFF = 3 - PAD;
    int sy0 = y + OFF, sx0 = xx + OFF;

    int ag = lane >> 3, alr = lane & 7;
    int a_row = (ag & 1) * 8 + alr, a_kb = (ag >> 1) * 16;
    int b_row = (ag >> 1) * 8 + alr, b_kb = (ag & 1) * 16;

    float acc[4][4][4];
#pragma unroll
    for (int i = 0; i < 4; i++)
#pragma unroll
        for (int j = 0; j < 4; j++)
#pragma unroll
            for (int k = 0; k < 4; k++) acc[i][j][k] = 0.f;

    auto stage = [&](int ch) {
        int tap = GATHER ? (ch >> 3) : 0;
        int ci0 = (GATHER ? (ch & 7) : ch) * 32;
        uint32_t base = smb + (uint32_t)(ch & 1) * (4 * ARRB);
        size_t asrc;
        if (GATHER) {
            int ky = tap / KW, kx = tap - (tap / KW) * KW;
            asrc = (((size_t)b * PADP + (sy0 + ky * DIL)) * PADP + (sx0 + kx * DIL)) * C_ + ci0;
        } else {
            asrc = (size_t)gp * KDIM + ci0;
        }
        size_t bsrc = GATHER ? (((size_t)tap * C_ + bco) * C_ + ci0)
                             : ((size_t)bco * KDIM + ci0);
        uint32_t drow = (uint32_t)row * (RSTR * 2);
#pragma unroll
        for (int s = 0; s < 2; s++) {
            int qq = q0 + s;                       // 16B quarter 0..3
            uint32_t doff = drow + qq * 16;
            cp16(base + 0 * ARRB + doff, ah + asrc + qq * 8);
            cp16(base + 1 * ARRB + doff, al + asrc + qq * 8);
            cp16(base + 2 * ARRB + doff, bh + bsrc + qq * 8);
            cp16(base + 3 * ARRB + doff, bl + bsrc + qq * 8);
        }
        cp_commit();
    };

    stage(0);
#pragma unroll 1
    for (int ch = 0; ch < NCH; ch++) {
        if (ch + 1 < NCH) { stage(ch + 1); cp_wait<1>(); }
        else              { cp_wait<0>(); }
        __syncthreads();
        uint32_t base = smb + (uint32_t)(ch & 1) * (4 * ARRB);
        uint32_t aH = base, aL = base + ARRB, bH = base + 2 * ARRB, bL = base + 3 * ARRB;
#pragma unroll
        for (int k16 = 0; k16 < 2; k16++) {
            uint32_t koff = k16 * 32;
            uint32_t bhf[8], blf[8];
#pragma unroll
            for (int h = 0; h < 2; h++) {
                int n0 = wn * 32 + h * 16;
                ldm_x4(&bhf[h * 4], bH + (uint32_t)((n0 + b_row) * (RSTR * 2)) + b_kb + koff);
                ldm_x4(&blf[h * 4], bL + (uint32_t)((n0 + b_row) * (RSTR * 2)) + b_kb + koff);
            }
#pragma unroll
            for (int mt = 0; mt < 4; mt++) {
                int m0 = wm * 64 + mt * 16;
                uint32_t af[4];
                ldm_x4(af, aH + (uint32_t)((m0 + a_row) * (RSTR * 2)) + a_kb + koff);
#pragma unroll
                for (int nt = 0; nt < 4; nt++) {
                    mma_bf16(acc[mt][nt], af, &bhf[nt * 2]);
                    mma_bf16(acc[mt][nt], af, &blf[nt * 2]);
                }
                ldm_x4(af, aL + (uint32_t)((m0 + a_row) * (RSTR * 2)) + a_kb + koff);
#pragma unroll
                for (int nt = 0; nt < 4; nt++)
                    mma_bf16(acc[mt][nt], af, &bhf[nt * 2]);
            }
        }
        __syncthreads();
    }

    // epilogue
#pragma unroll
    for (int mt = 0; mt < 4; mt++) {
#pragma unroll
        for (int nt = 0; nt < 4; nt++) {
            int co2 = wn * 32 + nt * 8 + (lane & 3) * 2;
            int co = coBase + co2;
            float bv0 = __ldg(bias + co), bv1 = __ldg(bias + co + 1);
#pragma unroll
            for (int rr = 0; rr < 2; rr++) {
                int pr = blockIdx.x * 128 + wm * 64 + mt * 16 + (lane >> 2) + rr * 8;
                float v0 = acc[mt][nt][rr * 2 + 0] + bv0;
                float v1 = acc[mt][nt][rr * 2 + 1] + bv1;
                if (EPI != EPI_STEP) { v0 = elu_f(v0); v1 = elu_f(v1); }
                if (EPI == EPI_CONV) {
                    size_t o = (size_t)pr * 1024 + co_off + co;
                    __nv_bfloat16 h0, l0, h1, l1;
                    split_bf16(v0, h0, l0);
                    split_bf16(v1, h1, l1);
                    *reinterpret_cast<__nv_bfloat162*>(oh + o) = {h0, h1};
                    *reinterpret_cast<__nv_bfloat162*>(ol + o) = {l0, l1};
                } else if (EPI == EPI_FUSION) {
                    size_t o = (size_t)pr * 256 + co;
                    *reinterpret_cast<float2*>(of + o) = {v0, v1};
                    __nv_bfloat16 h0, l0, h1, l1;
                    split_bf16(v0, h0, l0);
                    split_bf16(v1, h1, l1);
                    *reinterpret_cast<__nv_bfloat162*>(oh + o) = {h0, h1};
                    *reinterpret_cast<__nv_bfloat162*>(ol + o) = {l0, l1};
                } else {
                    size_t o = (size_t)pr * 256 + co;
                    *reinterpret_cast<float2*>(of + o) = {v0, v1};
                }
            }
        }
    }
}

// ---------------- LN stats over (C,H,W) per batch (deterministic) -----------
__global__ void __launch_bounds__(256)
stats_kernel(const float* __restrict__ ybuf) {
    int b = blockIdx.x, t = threadIdx.x;
    const float* p = ybuf + (size_t)b * 57600 + t;
    float s1 = 0.f, s2 = 0.f;
#pragma unroll 5
    for (int i = 0; i < 225; i++) {
        float v = p[i * 256];
        s1 += v; s2 = fmaf(v, v, s2);
    }
    __shared__ float red[256];
    red[t] = s1; __syncthreads();
    for (int off = 128; off > 0; off >>= 1) {
        if (t < off) red[t] += red[t + off];
        __syncthreads();
    }
    if (t == 0) g_statsY[b * 2 + 0] = red[0];
    __syncthreads();
    red[t] = s2; __syncthreads();
    for (int off = 128; off > 0; off >>= 1) {
        if (t < off) red[t] += red[t + off];
        __syncthreads();
    }
    if (t == 0) g_statsY[b * 2 + 1] = red[0];
}

// ---------------- per-step update (memory-bound; noise precomputed) ---------
__global__ void __launch_bounds__(256)
step_update_kernel(const float* __restrict__ ybuf,
                   float* __restrict__ xc,
                   __nv_bfloat16* __restrict__ xch,
                   __nv_bfloat16* __restrict__ xcl,
                   float* __restrict__ dout,
                   const float* __restrict__ sp_arr,
                   const float* __restrict__ ss_arr,
                   const float* __restrict__ rw_arr,
                   const float* __restrict__ prob_arr,
                   int step, int last)
{
    int b = blockIdx.x;
    int t = threadIdx.x;

    double n = (double)(C_ * HW_);
    double mu_d = (double)g_statsY[b * 2 + 0] / n;
    double var_d = (double)g_statsY[b * 2 + 1] / n - mu_d * mu_d;
    float mu = (float)mu_d;
    float rs = (float)(1.0 / sqrt(var_d + 1e-5));

    float sp = sp_arr[step];
    float cns = prob_arr[step] * ss_arr[step];
    float rw1 = 1.f + rw_arr[step];

    size_t bbase = (size_t)b * 57600;
    const float* nz = g_nz + (size_t)step * NELEM + bbase;

    float s1 = 0.f, s2 = 0.f;
#pragma unroll
    for (int e = 0; e < 15; e++) {
        int p = blockIdx.y * 15 + e;
        int j = p * 256 + t;
        float yv = ybuf[bbase + j];
        float d = (yv - mu) * rs;
        d = fmaf(d, g_lnwt[j], g_lnbt[j]);
        d = elu_f(d);
        s1 += d; s2 = fmaf(d, d, s2);
        float u = nz[j];
        float xn = fmaf(xc[bbase + j], rw1, fmaf(d, sp, u * cns));
        if (last) {
            dout[((size_t)b * 256 + t) * 225 + p] = xn;
        } else {
            xc[bbase + j] = xn;
            __nv_bfloat16 h, l;
            split_bf16(xn, h, l);
            xch[bbase + j] = h;
            xcl[bbase + j] = l;
        }
    }

    __shared__ float red[256];
    red[t] = s1; __syncthreads();
    for (int off = 128; off > 0; off >>= 1) {
        if (t < off) red[t] += red[t + off];
        __syncthreads();
    }
    if (t == 0) g_stats2[(b * UPD_BLOCKS + blockIdx.y) * 2 + 0] = red[0];
    __syncthreads();
    red[t] = s2; __syncthreads();
    for (int off = 128; off > 0; off >>= 1) {
        if (t < off) red[t] += red[t + off];
        __syncthreads();
    }
    if (t == 0) g_stats2[(b * UPD_BLOCKS + blockIdx.y) * 2 + 1] = red[0];
}

__global__ void var_final_kernel(float* __restrict__ out_var, int step) {
    int b = threadIdx.x;
    double s1 = 0.0, s2 = 0.0;
    for (int k = 0; k < UPD_BLOCKS; k++) {
        s1 += (double)g_stats2[(b * UPD_BLOCKS + k) * 2 + 0];
        s2 += (double)g_stats2[(b * UPD_BLOCKS + k) * 2 + 1];
    }
    const double n = (double)(C_ * HW_);
    double v = (s2 - s1 * s1 / n) / (n - 1.0);
    out_var[b * S_ + step] = (float)v;
}

// ---------------- launch ----------------------------------------------------
extern "C" void kernel_launch(void* const* d_in, const int* in_sizes, int n_in,
                              void* d_out, int out_size) {
    const float* x    = (const float*)d_in[0];
    const float* prob = (const float*)d_in[1];
    const float* w3   = (const float*)d_in[2];
    const float* b3   = (const float*)d_in[3];
    const float* w3d  = (const float*)d_in[4];
    const float* b3d  = (const float*)d_in[5];
    const float* w5   = (const float*)d_in[6];
    const float* b5   = (const float*)d_in[7];
    const float* w7   = (const float*)d_in[8];
    const float* b7   = (const float*)d_in[9];
    const float* wf   = (const float*)d_in[10];
    const float* bf   = (const float*)d_in[11];
    const float* w1   = (const float*)d_in[12];
    const float* b1   = (const float*)d_in[13];
    const float* lnw  = (const float*)d_in[14];
    const float* lnb  = (const float*)d_in[15];
    const float* spar = (const float*)d_in[16];
    const float* ssc  = (const float*)d_in[17];
    const float* rwv  = (const float*)d_in[18];

    float* out = (float*)d_out;
    float* out_var = out + (size_t)NELEM;

    __nv_bfloat16 *xph, *xpl, *wh, *wl, *wfh, *wfl, *w1h, *w1l, *cath, *catl, *xch, *xcl;
    float *xc, *ybuf;
    cudaGetSymbolAddress((void**)&xph, g_xph);
    cudaGetSymbolAddress((void**)&xpl, g_xpl);
    cudaGetSymbolAddress((void**)&wh, g_wh);
    cudaGetSymbolAddress((void**)&wl, g_wl);
    cudaGetSymbolAddress((void**)&wfh, g_wfh);
    cudaGetSymbolAddress((void**)&wfl, g_wfl);
    cudaGetSymbolAddress((void**)&w1h, g_w1h);
    cudaGetSymbolAddress((void**)&w1l, g_w1l);
    cudaGetSymbolAddress((void**)&cath, g_cath);
    cudaGetSymbolAddress((void**)&catl, g_catl);
    cudaGetSymbolAddress((void**)&xch, g_xch);
    cudaGetSymbolAddress((void**)&xcl, g_xcl);
    cudaGetSymbolAddress((void**)&xc, g_xc);
    cudaGetSymbolAddress((void**)&ybuf, g_ybuf);

    static cudaStream_t s2 = nullptr;
    static cudaEvent_t evF;
    static cudaEvent_t evN[S_];
    if (!s2) {
        cudaStreamCreate(&s2);
        cudaEventCreateWithFlags(&evF, cudaEventDisableTiming);
        for (int i = 0; i < S_; i++) cudaEventCreateWithFlags(&evN[i], cudaEventDisableTiming);
    }

    cudaFuncSetAttribute(hmma_kernel<3, 3, 1, 1, 256, EPI_CONV, true>,
                         cudaFuncAttributeMaxDynamicSharedMemorySize, HMMA_SMEM);
    cudaFuncSetAttribute(hmma_kernel<3, 3, 2, 2, 256, EPI_CONV, true>,
                         cudaFuncAttributeMaxDynamicSharedMemorySize, HMMA_SMEM);
    cudaFuncSetAttribute(hmma_kernel<5, 5, 1, 2, 256, EPI_CONV, true>,
                         cudaFuncAttributeMaxDynamicSharedMemorySize, HMMA_SMEM);
    cudaFuncSetAttribute(hmma_kernel<7, 7, 1, 3, 256, EPI_CONV, true>,
                         cudaFuncAttributeMaxDynamicSharedMemorySize, HMMA_SMEM);
    cudaFuncSetAttribute(hmma_kernel<1, 1, 1, 3, 1024, EPI_FUSION, false>,
                         cudaFuncAttributeMaxDynamicSharedMemorySize, HMMA_SMEM);
    cudaFuncSetAttribute(hmma_kernel<1, 1, 1, 3, 256, EPI_STEP, false>,
                         cudaFuncAttributeMaxDynamicSharedMemorySize, HMMA_SMEM);

    // fork: noise generation for all 8 steps on stream 2
    cudaEventRecord(evF, 0);
    cudaStreamWaitEvent(s2, evF, 0);
    for (int s = 0; s < S_; s++) {
        noise_kernel<<<dim3(B_, 15), 256, 0, s2>>>(s);
        cudaEventRecord(evN[s], s2);
    }

    // prep
    pad_split_kernel<<<dim3(B_, PADP * PADP), 256>>>(x);
    wsplit_kernel<<<(C_ * C_ * 9 + 255) / 256, 256>>>(w3, 9, 0);
    wsplit_kernel<<<(C_ * C_ * 9 + 255) / 256, 256>>>(w3d, 9, 9);
    wsplit_kernel<<<(C_ * C_ * 25 + 255) / 256, 256>>>(w5, 25, 18);
    wsplit_kernel<<<(C_ * C_ * 49 + 255) / 256, 256>>>(w7, 49, 43);
    wsplit1_kernel<<<(4 * C_ * C_ + 255) / 256, 256>>>(wf, wfh, wfl, 4 * C_ * C_);
    wsplit1_kernel<<<(C_ * C_ + 255) / 256, 256>>>(w1, w1h, w1l, C_ * C_);
    lnT_kernel<<<HW_, 256>>>(lnw, lnb);

    // multi-scale perception -> concat (channels-last split bf16)
    dim3 g(450, 2);
    hmma_kernel<3, 3, 1, 1, 256, EPI_CONV, true><<<g, 256, HMMA_SMEM>>>(
        xph, xpl, wh + (size_t)0 * C_ * C_, wl + (size_t)0 * C_ * C_, b3,
        cath, catl, nullptr, 0);
    hmma_kernel<3, 3, 2, 2, 256, EPI_CONV, true><<<g, 256, HMMA_SMEM>>>(
        xph, xpl, wh + (size_t)9 * C_ * C_, wl + (size_t)9 * C_ * C_, b3d,
        cath, catl, nullptr, 256);
    hmma_kernel<5, 5, 1, 2, 256, EPI_CONV, true><<<g, 256, HMMA_SMEM>>>(
        xph, xpl, wh + (size_t)18 * C_ * C_, wl + (size_t)18 * C_ * C_, b5,
        cath, catl, nullptr, 512);
    hmma_kernel<7, 7, 1, 3, 256, EPI_CONV, true><<<g, 256, HMMA_SMEM>>>(
        xph, xpl, wh + (size_t)43 * C_ * C_, wl + (size_t)43 * C_ * C_, b7,
        cath, catl, nullptr, 768);

    // fusion GEMM (K=1024) -> xc fp32 + split
    hmma_kernel<1, 1, 1, 3, 1024, EPI_FUSION, false><<<g, 256, HMMA_SMEM>>>(
        cath, catl, wfh, wfl, bf, xch, xcl, xc, 0);

    // 8 NCA steps
    for (int i = 0; i < S_; i++) {
        hmma_kernel<1, 1, 1, 3, 256, EPI_STEP, false><<<g, 256, HMMA_SMEM>>>(
            xch, xcl, w1h, w1l, b1, nullptr, nullptr, ybuf, 0);
        stats_kernel<<<B_, 256>>>(ybuf);
        cudaStreamWaitEvent(0, evN[i], 0);
        step_update_kernel<<<dim3(B_, UPD_BLOCKS), 256>>>(
            ybuf, xc, xch, xcl, out, spar, ssc, rwv, prob, i, i == S_ - 1);
        var_final_kernel<<<1, 256>>>(out_var, i);
    }
}

// round 11
// speedup vs baseline: 6.6184x; 1.5695x over previous
#include <cuda_runtime.h>
#include <cuda_fp16.h>
#include <cstdint>
#include <math.h>

#define DINLINE __device__ __forceinline__

constexpr int B_ = 256;
constexpr int C_ = 256;
constexpr int HW_ = 225;
constexpr int S_ = 8;
constexpr int NELEM = B_ * C_ * HW_;      // 14,745,600
constexpr int NPIX = B_ * HW_;            // 57600
constexpr int UPD_BLOCKS = 15;
constexpr int PADP = 21;
constexpr int TAPS_TOTAL = 92;
constexpr int MTILES = 450;               // 57600 / 128

// ---------------- scratch ---------------------------------------------------
__device__ __half g_xph[(size_t)B_ * PADP * PADP * C_];
__device__ __half g_wh[(size_t)TAPS_TOTAL * C_ * C_];
__device__ __half g_wl[(size_t)TAPS_TOTAL * C_ * C_];
__device__ __half g_wfh[4 * C_ * C_];
__device__ __half g_wfl[4 * C_ * C_];
__device__ __half g_w1h[C_ * C_];
__device__ __half g_w1l[C_ * C_];
__device__ __half g_cath[(size_t)NPIX * 1024];     // channels-last concat (fp16)
__device__ float g_xc[NELEM];                       // channels-last [b][p][c]
__device__ __half g_xch[NELEM];
__device__ float g_ybuf[NELEM];                     // channels-last
__device__ float g_nz[(size_t)S_ * NELEM];          // noise, channels-last
__device__ float g_lnwt[C_ * HW_];                  // [p][c]
__device__ float g_lnbt[C_ * HW_];
__device__ float g_stats3[2 * MTILES * 4];          // y-stat partials per CTA
__device__ float g_mu[B_], g_rs[B_];
__device__ float g_stats2[(size_t)S_ * B_ * UPD_BLOCKS * 2];

// conv parameter tables (compile-time constants)
__constant__ int c_taps[4]   = {9, 9, 25, 49};
__constant__ int c_kw[4]     = {3, 3, 5, 7};
__constant__ int c_dil[4]    = {1, 2, 1, 1};
__constant__ int c_pad[4]    = {1, 2, 2, 3};
__constant__ int c_tapoff[4] = {0, 9, 18, 43};
__constant__ int c_cooff[4]  = {0, 256, 512, 768};

// ---------------- helpers ---------------------------------------------------
DINLINE float elu_f(float v) { return v > 0.f ? v : expm1f(v); }
DINLINE uint32_t rotl32(uint32_t v, int s) { return __funnelshift_l(v, v, s); }

DINLINE void threefry2x32(uint32_t k0, uint32_t k1, uint32_t& x0, uint32_t& x1) {
    uint32_t k2 = k0 ^ k1 ^ 0x1BD11BDAu;
    x0 += k0; x1 += k1;
#define TF_R(r) { x0 += x1; x1 = rotl32(x1, r); x1 ^= x0; }
    TF_R(13) TF_R(15) TF_R(26) TF_R(6)
    x0 += k1; x1 += k2 + 1u;
    TF_R(17) TF_R(29) TF_R(16) TF_R(24)
    x0 += k2; x1 += k0 + 2u;
    TF_R(13) TF_R(15) TF_R(26) TF_R(6)
    x0 += k0; x1 += k1 + 3u;
    TF_R(17) TF_R(29) TF_R(16) TF_R(24)
    x0 += k1; x1 += k2 + 4u;
    TF_R(13) TF_R(15) TF_R(26) TF_R(6)
    x0 += k2; x1 += k0 + 5u;
#undef TF_R
}

DINLINE uint32_t smem_to_u32(const void* p) {
    uint32_t a;
    asm("{ .reg .u64 t; cvta.to.shared.u64 t, %1; cvt.u32.u64 %0, t; }"
        : "=r"(a) : "l"(p));
    return a;
}
DINLINE void ldm_x4(uint32_t* r, uint32_t addr) {
    asm volatile("ldmatrix.sync.aligned.m8n8.x4.shared.b16 {%0,%1,%2,%3}, [%4];"
                 : "=r"(r[0]), "=r"(r[1]), "=r"(r[2]), "=r"(r[3]) : "r"(addr));
}
DINLINE void mma_f16(float* c, const uint32_t* a, const uint32_t* b) {
    asm volatile(
        "mma.sync.aligned.m16n8k16.row.col.f32.f16.f16.f32 "
        "{%0,%1,%2,%3}, {%4,%5,%6,%7}, {%8,%9}, {%0,%1,%2,%3};"
        : "+f"(c[0]), "+f"(c[1]), "+f"(c[2]), "+f"(c[3])
        : "r"(a[0]), "r"(a[1]), "r"(a[2]), "r"(a[3]), "r"(b[0]), "r"(b[1]));
}
DINLINE void cp16(uint32_t dst, const void* src) {
    asm volatile("cp.async.cg.shared.global [%0], [%1], 16;" :: "r"(dst), "l"(src));
}
DINLINE void cp_commit() { asm volatile("cp.async.commit_group;"); }
template <int N> DINLINE void cp_wait() { asm volatile("cp.async.wait_group %0;" :: "n"(N)); }

DINLINE void split_fp16(float v, __half& h, __half& l) {
    h = __float2half_rn(v);
    l = __float2half_rn(v - __half2float(h));
}

// ---------------- prep kernels ----------------------------------------------
__global__ void pad_h_kernel(const float* __restrict__ x) {
    int c = threadIdx.x;
    int b = blockIdx.x;
    int pp = blockIdx.y;
    int py = pp / PADP, px = pp - py * PADP;
    float v = 0.f;
    int iy = py - 3, ix = px - 3;
    if (iy >= 0 && iy < 15 && ix >= 0 && ix < 15)
        v = x[((size_t)b * C_ + c) * HW_ + iy * 15 + ix];
    g_xph[((size_t)b * (PADP * PADP) + pp) * C_ + c] = __float2half_rn(v);
}

__global__ void wsplit_kernel(const float* __restrict__ w, int taps, int tap_off) {
    int idx = blockIdx.x * 256 + threadIdx.x;
    if (idx >= C_ * C_ * taps) return;
    int tap = idx % taps;
    int rest = idx / taps;
    int ci = rest & 255;
    int co = rest >> 8;
    __half h, l;
    split_fp16(w[idx], h, l);
    size_t o = ((size_t)(tap_off + tap) * C_ + co) * C_ + ci;
    g_wh[o] = h;
    g_wl[o] = l;
}

__global__ void wsplit1_kernel(const float* __restrict__ w,
                               __half* __restrict__ h, __half* __restrict__ l, int n) {
    int idx = blockIdx.x * 256 + threadIdx.x;
    if (idx >= n) return;
    split_fp16(w[idx], h[idx], l[idx]);
}

__global__ void lnT_kernel(const float* __restrict__ lnw, const float* __restrict__ lnb) {
    int p = blockIdx.x, c = threadIdx.x;
    g_lnwt[p * 256 + c] = lnw[c * 225 + p];
    g_lnbt[p * 256 + c] = lnb[c * 225 + p];
}

// ---------------- noise pre-generation (stream 2) ---------------------------
__global__ void __launch_bounds__(256)
noise_kernel(int step) {
    int b = blockIdx.x, yb = blockIdx.y, t = threadIdx.x;
    uint32_t fk0 = 0u, fk1 = (uint32_t)step;
    threefry2x32(0u, 42u, fk0, fk1);
    float* o = g_nz + (size_t)step * NELEM + (size_t)b * 57600;
#pragma unroll
    for (int e = 0; e < 15; e++) {
        int p = yb * 15 + e;
        uint32_t c0 = 0u, c1 = (uint32_t)((b * 256 + t) * 225 + p);
        threefry2x32(fk0, fk1, c0, c1);
        uint32_t bits = c0 ^ c1;
        o[p * 256 + t] = __uint_as_float(0x3f800000u | (bits >> 9)) - 1.0f;
    }
}

// ---------------- unified HMMA kernel (fp16 2-term split) --------------------
// CTA 128 px x 128 ch; 8 warps 2x4, warp 64x32. 3-stage cp.async, 1 sync/chunk.
// acc = Ah*Bh + Ah*Bl  (A hi-only fp16, B split fp16 hi/lo).
constexpr int EPI_CONV = 0, EPI_FUSION = 1, EPI_STEP = 2;
constexpr int RSTR = 40;                    // fp16 per row (80B)
constexpr int ARRB = 128 * RSTR * 2;        // 10240 B
constexpr int CHUNKB = 3 * ARRB;            // Ah, Bh, Bl
constexpr int HMMA_SMEM = 3 * CHUNKB;       // 92160

template <int KDIM, int EPI, bool GATHER>
__global__ void __launch_bounds__(256, 2)
hmma_kernel(const __half* __restrict__ A,
            const __half* __restrict__ BH, const __half* __restrict__ BL,
            const float* __restrict__ bs0, const float* __restrict__ bs1,
            const float* __restrict__ bs2, const float* __restrict__ bs3,
            __half* __restrict__ oh, float* __restrict__ of)
{
    extern __shared__ __align__(16) char sm[];
    uint32_t smb = smem_to_u32(sm);

    int z = GATHER ? blockIdx.z : 0;
    int taps = GATHER ? c_taps[z] : 1;
    int kw = GATHER ? c_kw[z] : 1;
    int dil = GATHER ? c_dil[z] : 1;
    int off0 = GATHER ? (3 - c_pad[z]) : 0;
    int tap_off = GATHER ? c_tapoff[z] : 0;
    int co_off = GATHER ? c_cooff[z] : 0;
    int NCH = GATHER ? taps * 8 : KDIM / 32;
    const float* bias = (z == 0) ? bs0 : (z == 1) ? bs1 : (z == 2) ? bs2 : bs3;

    int t = threadIdx.x, lane = t & 31, wid = t >> 5;
    int wm = wid >> 2, wn = wid & 3;
    int row = t >> 1, q0 = (t & 1) * 2;
    int gp = blockIdx.x * 128 + row;
    int b = gp / 225, rem = gp - b * 225, y = rem / 15, xx = rem - y * 15;
    int coBase = blockIdx.y * 128;
    int bco = coBase + row;
    int sy0 = y + off0, sx0 = xx + off0;

    int ag = lane >> 3, alr = lane & 7;
    int a_row = (ag & 1) * 8 + alr, a_kb = (ag >> 1) * 16;
    int b_row = (ag >> 1) * 8 + alr, b_kb = (ag & 1) * 16;

    float acc[4][4][4];
#pragma unroll
    for (int i = 0; i < 4; i++)
#pragma unroll
        for (int j = 0; j < 4; j++)
#pragma unroll
            for (int k = 0; k < 4; k++) acc[i][j][k] = 0.f;

    auto stage = [&](int ch) {
        int tap = GATHER ? (ch >> 3) : 0;
        int ci0 = (GATHER ? (ch & 7) : ch) * 32;
        uint32_t base = smb + (uint32_t)(ch % 3) * CHUNKB;
        size_t asrc;
        if (GATHER) {
            int ky = tap / kw, kx = tap - ky * kw;
            asrc = (((size_t)b * PADP + (sy0 + ky * dil)) * PADP + (sx0 + kx * dil)) * C_ + ci0;
        } else {
            asrc = (size_t)gp * KDIM + ci0;
        }
        size_t bsrc = GATHER ? (((size_t)(tap_off + tap) * C_ + bco) * C_ + ci0)
                             : ((size_t)bco * KDIM + ci0);
        uint32_t drow = (uint32_t)row * (RSTR * 2);
#pragma unroll
        for (int s = 0; s < 2; s++) {
            int qq = q0 + s;
            uint32_t doff = drow + qq * 16;
            cp16(base + 0 * ARRB + doff, A + asrc + qq * 8);
            cp16(base + 1 * ARRB + doff, BH + bsrc + qq * 8);
            cp16(base + 2 * ARRB + doff, BL + bsrc + qq * 8);
        }
        cp_commit();
    };

    stage(0);
    stage(1);
#pragma unroll 1
    for (int ch = 0; ch < NCH; ch++) {
        cp_wait<1>();
        __syncthreads();
        uint32_t base = smb + (uint32_t)(ch % 3) * CHUNKB;
        uint32_t aH = base, bH = base + ARRB, bL = base + 2 * ARRB;
#pragma unroll
        for (int k16 = 0; k16 < 2; k16++) {
            uint32_t koff = k16 * 32;
            uint32_t bhf[8], blf[8];
#pragma unroll
            for (int h = 0; h < 2; h++) {
                int n0 = wn * 32 + h * 16;
                ldm_x4(&bhf[h * 4], bH + (uint32_t)((n0 + b_row) * (RSTR * 2)) + b_kb + koff);
                ldm_x4(&blf[h * 4], bL + (uint32_t)((n0 + b_row) * (RSTR * 2)) + b_kb + koff);
            }
#pragma unroll
            for (int mt = 0; mt < 4; mt++) {
                int m0 = wm * 64 + mt * 16;
                uint32_t af[4];
                ldm_x4(af, aH + (uint32_t)((m0 + a_row) * (RSTR * 2)) + a_kb + koff);
#pragma unroll
                for (int nt = 0; nt < 4; nt++) {
                    mma_f16(acc[mt][nt], af, &bhf[nt * 2]);
                    mma_f16(acc[mt][nt], af, &blf[nt * 2]);
                }
            }
        }
        if (ch + 2 < NCH) stage(ch + 2);
        else cp_commit();
    }

    // epilogue
    float sst[2][2] = {{0.f, 0.f}, {0.f, 0.f}};
    int bstart = (blockIdx.x * 128) / 225;
#pragma unroll
    for (int mt = 0; mt < 4; mt++) {
#pragma unroll
        for (int nt = 0; nt < 4; nt++) {
            int co2 = wn * 32 + nt * 8 + (lane & 3) * 2;
            int co = coBase + co2;
            float bv0 = __ldg(bias + co), bv1 = __ldg(bias + co + 1);
#pragma unroll
            for (int rr = 0; rr < 2; rr++) {
                int pr = blockIdx.x * 128 + wm * 64 + mt * 16 + (lane >> 2) + rr * 8;
                float v0 = acc[mt][nt][rr * 2 + 0] + bv0;
                float v1 = acc[mt][nt][rr * 2 + 1] + bv1;
                if (EPI != EPI_STEP) { v0 = elu_f(v0); v1 = elu_f(v1); }
                if (EPI == EPI_CONV) {
                    size_t o = (size_t)pr * 1024 + co_off + co;
                    *reinterpret_cast<__half2*>(oh + o) = __floats2half2_rn(v0, v1);
                } else if (EPI == EPI_FUSION) {
                    size_t o = (size_t)pr * 256 + co;
                    *reinterpret_cast<float2*>(of + o) = {v0, v1};
                    *reinterpret_cast<__half2*>(oh + o) = __floats2half2_rn(v0, v1);
                } else {
                    size_t o = (size_t)pr * 256 + co;
                    *reinterpret_cast<float2*>(of + o) = {v0, v1};
                    int slot = pr / 225 - bstart;
                    sst[slot][0] += v0 + v1;
                    sst[slot][1] += v0 * v0 + v1 * v1;
                }
            }
        }
    }

    if (EPI == EPI_STEP) {
        // deterministic block-tree reduction of 4 partials in (now free) smem
        __syncthreads();
        float* red = reinterpret_cast<float*>(sm);
        red[t * 4 + 0] = sst[0][0];
        red[t * 4 + 1] = sst[0][1];
        red[t * 4 + 2] = sst[1][0];
        red[t * 4 + 3] = sst[1][1];
        __syncthreads();
        for (int o2 = 128; o2 > 0; o2 >>= 1) {
            if (t < o2) {
#pragma unroll
                for (int k = 0; k < 4; k++) red[t * 4 + k] += red[(t + o2) * 4 + k];
            }
            __syncthreads();
        }
        if (t == 0) {
            int cta = blockIdx.y * MTILES + blockIdx.x;
#pragma unroll
            for (int k = 0; k < 4; k++) g_stats3[cta * 4 + k] = red[k];
        }
    }
}

// ---------------- combine y-stat partials -> mu, rsqrt per batch ------------
__global__ void combine_kernel() {
    int b = threadIdx.x;
    double s1 = 0.0, s2 = 0.0;
    int cxlo = (225 * b) >> 7;
    int cxhi = (225 * b + 224) >> 7;
    for (int cx = cxlo; cx <= cxhi; cx++) {
        int bstart = (cx * 128) / 225;
        int slot = b - bstart;
        if (slot >= 0 && slot < 2) {
            for (int cy = 0; cy < 2; cy++) {
                s1 += (double)g_stats3[(cy * MTILES + cx) * 4 + slot * 2 + 0];
                s2 += (double)g_stats3[(cy * MTILES + cx) * 4 + slot * 2 + 1];
            }
        }
    }
    const double n = (double)(C_ * HW_);
    double mu = s1 / n;
    double var = s2 / n - mu * mu;
    g_mu[b] = (float)mu;
    g_rs[b] = (float)(1.0 / sqrt(var + 1e-5));
}

// ---------------- per-step update (noise precomputed) -----------------------
__global__ void __launch_bounds__(256)
step_update_kernel(const float* __restrict__ ybuf,
                   float* __restrict__ xc,
                   __half* __restrict__ xch,
                   float* __restrict__ dout,
                   const float* __restrict__ sp_arr,
                   const float* __restrict__ ss_arr,
                   const float* __restrict__ rw_arr,
                   const float* __restrict__ prob_arr,
                   int step, int last)
{
    int b = blockIdx.x;
    int t = threadIdx.x;

    float mu = g_mu[b];
    float rs = g_rs[b];
    float sp = sp_arr[step];
    float cns = prob_arr[step] * ss_arr[step];
    float rw1 = 1.f + rw_arr[step];

    size_t bbase = (size_t)b * 57600;
    const float* nz = g_nz + (size_t)step * NELEM + bbase;

    float s1 = 0.f, s2 = 0.f;
#pragma unroll
    for (int e = 0; e < 15; e++) {
        int p = blockIdx.y * 15 + e;
        int j = p * 256 + t;
        float yv = ybuf[bbase + j];
        float d = (yv - mu) * rs;
        d = fmaf(d, g_lnwt[j], g_lnbt[j]);
        d = elu_f(d);
        s1 += d; s2 = fmaf(d, d, s2);
        float u = nz[j];
        float xn = fmaf(xc[bbase + j], rw1, fmaf(d, sp, u * cns));
        if (last) {
            dout[((size_t)b * 256 + t) * 225 + p] = xn;
        } else {
            xc[bbase + j] = xn;
            xch[bbase + j] = __float2half_rn(xn);
        }
    }

    __shared__ float red[256];
    red[t] = s1; __syncthreads();
    for (int off = 128; off > 0; off >>= 1) {
        if (t < off) red[t] += red[t + off];
        __syncthreads();
    }
    size_t sbase = ((size_t)step * B_ + b) * UPD_BLOCKS;
    if (t == 0) g_stats2[(sbase + blockIdx.y) * 2 + 0] = red[0];
    __syncthreads();
    red[t] = s2; __syncthreads();
    for (int off = 128; off > 0; off >>= 1) {
        if (t < off) red[t] += red[t + off];
        __syncthreads();
    }
    if (t == 0) g_stats2[(sbase + blockIdx.y) * 2 + 1] = red[0];
}

// ---------------- all-steps unbiased variance (single launch at end) --------
__global__ void var_final_kernel(float* __restrict__ out_var) {
    int step = blockIdx.x;
    int b = threadIdx.x;
    double s1 = 0.0, s2 = 0.0;
    size_t sbase = ((size_t)step * B_ + b) * UPD_BLOCKS;
    for (int k = 0; k < UPD_BLOCKS; k++) {
        s1 += (double)g_stats2[(sbase + k) * 2 + 0];
        s2 += (double)g_stats2[(sbase + k) * 2 + 1];
    }
    const double n = (double)(C_ * HW_);
    double v = (s2 - s1 * s1 / n) / (n - 1.0);
    out_var[b * S_ + step] = (float)v;
}

// ---------------- launch ----------------------------------------------------
extern "C" void kernel_launch(void* const* d_in, const int* in_sizes, int n_in,
                              void* d_out, int out_size) {
    const float* x    = (const float*)d_in[0];
    const float* prob = (const float*)d_in[1];
    const float* w3   = (const float*)d_in[2];
    const float* b3   = (const float*)d_in[3];
    const float* w3d  = (const float*)d_in[4];
    const float* b3d  = (const float*)d_in[5];
    const float* w5   = (const float*)d_in[6];
    const float* b5   = (const float*)d_in[7];
    const float* w7   = (const float*)d_in[8];
    const float* b7   = (const float*)d_in[9];
    const float* wf   = (const float*)d_in[10];
    const float* bf   = (const float*)d_in[11];
    const float* w1   = (const float*)d_in[12];
    const float* b1   = (const float*)d_in[13];
    const float* lnw  = (const float*)d_in[14];
    const float* lnb  = (const float*)d_in[15];
    const float* spar = (const float*)d_in[16];
    const float* ssc  = (const float*)d_in[17];
    const float* rwv  = (const float*)d_in[18];

    float* out = (float*)d_out;
    float* out_var = out + (size_t)NELEM;

    __half *xph, *wh, *wl, *wfh, *wfl, *w1h, *w1l, *cath, *xch;
    float *xc, *ybuf;
    cudaGetSymbolAddress((void**)&xph, g_xph);
    cudaGetSymbolAddress((void**)&wh, g_wh);
    cudaGetSymbolAddress((void**)&wl, g_wl);
    cudaGetSymbolAddress((void**)&wfh, g_wfh);
    cudaGetSymbolAddress((void**)&wfl, g_wfl);
    cudaGetSymbolAddress((void**)&w1h, g_w1h);
    cudaGetSymbolAddress((void**)&w1l, g_w1l);
    cudaGetSymbolAddress((void**)&cath, g_cath);
    cudaGetSymbolAddress((void**)&xch, g_xch);
    cudaGetSymbolAddress((void**)&xc, g_xc);
    cudaGetSymbolAddress((void**)&ybuf, g_ybuf);

    static cudaStream_t s2 = nullptr;
    static cudaEvent_t evF;
    static cudaEvent_t evN[S_];
    if (!s2) {
        cudaStreamCreate(&s2);
        cudaEventCreateWithFlags(&evF, cudaEventDisableTiming);
        for (int i = 0; i < S_; i++) cudaEventCreateWithFlags(&evN[i], cudaEventDisableTiming);
    }

    cudaFuncSetAttribute(hmma_kernel<256, EPI_CONV, true>,
                         cudaFuncAttributeMaxDynamicSharedMemorySize, HMMA_SMEM);
    cudaFuncSetAttribute(hmma_kernel<1024, EPI_FUSION, false>,
                         cudaFuncAttributeMaxDynamicSharedMemorySize, HMMA_SMEM);
    cudaFuncSetAttribute(hmma_kernel<256, EPI_STEP, false>,
                         cudaFuncAttributeMaxDynamicSharedMemorySize, HMMA_SMEM);

    // fork: noise generation for all 8 steps on stream 2
    cudaEventRecord(evF, 0);
    cudaStreamWaitEvent(s2, evF, 0);
    for (int s = 0; s < S_; s++) {
        noise_kernel<<<dim3(B_, 15), 256, 0, s2>>>(s);
        cudaEventRecord(evN[s], s2);
    }

    // prep
    pad_h_kernel<<<dim3(B_, PADP * PADP), 256>>>(x);
    wsplit_kernel<<<(C_ * C_ * 9 + 255) / 256, 256>>>(w3, 9, 0);
    wsplit_kernel<<<(C_ * C_ * 9 + 255) / 256, 256>>>(w3d, 9, 9);
    wsplit_kernel<<<(C_ * C_ * 25 + 255) / 256, 256>>>(w5, 25, 18);
    wsplit_kernel<<<(C_ * C_ * 49 + 255) / 256, 256>>>(w7, 49, 43);
    wsplit1_kernel<<<(4 * C_ * C_ + 255) / 256, 256>>>(wf, wfh, wfl, 4 * C_ * C_);
    wsplit1_kernel<<<(C_ * C_ + 255) / 256, 256>>>(w1, w1h, w1l, C_ * C_);
    lnT_kernel<<<HW_, 256>>>(lnw, lnb);

    // all 4 multi-scale convs in ONE launch (z = conv id) -> cat (fp16)
    hmma_kernel<256, EPI_CONV, true><<<dim3(MTILES, 2, 4), 256, HMMA_SMEM>>>(
        xph, wh, wl, b3, b3d, b5, b7, cath, nullptr);

    // fusion GEMM (K=1024) -> xc fp32 + xch fp16
    hmma_kernel<1024, EPI_FUSION, false><<<dim3(MTILES, 2), 256, HMMA_SMEM>>>(
        cath, wfh, wfl, bf, bf, bf, bf, xch, xc);

    // 8 NCA steps: GEMM(+y-stat partials) -> combine -> update
    for (int i = 0; i < S_; i++) {
        hmma_kernel<256, EPI_STEP, false><<<dim3(MTILES, 2), 256, HMMA_SMEM>>>(
            xch, w1h, w1l, b1, b1, b1, b1, nullptr, ybuf);
        combine_kernel<<<1, 256>>>();
        cudaStreamWaitEvent(0, evN[i], 0);
        step_update_kernel<<<dim3(B_, UPD_BLOCKS), 256>>>(
            ybuf, xc, xch, out, spar, ssc, rwv, prob, i, i == S_ - 1);
    }
    var_final_kernel<<<S_, 256>>>(out_var);
}

// round 12
// speedup vs baseline: 8.5050x; 1.2850x over previous
#include <cuda_runtime.h>
#include <cuda_fp16.h>
#include <cstdint>
#include <math.h>

#define DINLINE __device__ __forceinline__

constexpr int B_ = 256;
constexpr int C_ = 256;
constexpr int HW_ = 225;
constexpr int S_ = 8;
constexpr int NELEM = B_ * C_ * HW_;      // 14,745,600
constexpr int NPIX = B_ * HW_;            // 57600
constexpr int UPD_BLOCKS = 15;
constexpr int PADP = 21;
constexpr int TAPS_TOTAL = 92;
constexpr int MTILES = 450;               // 57600 / 128

// ---------------- scratch ---------------------------------------------------
__device__ __half g_xph[(size_t)B_ * PADP * PADP * C_];
__device__ __half g_wh[(size_t)TAPS_TOTAL * C_ * C_];
__device__ __half g_wfh[4 * C_ * C_];
__device__ __half g_wfl[4 * C_ * C_];
__device__ __half g_w1h[C_ * C_];
__device__ __half g_w1l[C_ * C_];
__device__ __half g_cath[(size_t)NPIX * 1024];     // channels-last concat (fp16)
__device__ float g_xc[NELEM];                       // channels-last [b][p][c]
__device__ __half g_xch[NELEM];
__device__ float g_ybuf[NELEM];                     // channels-last
__device__ float g_nz[(size_t)S_ * NELEM];          // noise, channels-last
__device__ float g_lnwt[C_ * HW_];                  // [p][c]
__device__ float g_lnbt[C_ * HW_];
__device__ float g_stats3[2 * MTILES * 4];          // y-stat partials per CTA
__device__ float g_stats2[(size_t)S_ * B_ * UPD_BLOCKS * 2];

// conv parameter tables
__constant__ int c_taps[4]   = {9, 9, 25, 49};
__constant__ int c_kw[4]     = {3, 3, 5, 7};
__constant__ int c_dil[4]    = {1, 2, 1, 1};
__constant__ int c_pad[4]    = {1, 2, 2, 3};
__constant__ int c_tapoff[4] = {0, 9, 18, 43};
__constant__ int c_cooff[4]  = {0, 256, 512, 768};

// ---------------- helpers ---------------------------------------------------
DINLINE float elu_f(float v) { return v > 0.f ? v : expm1f(v); }
DINLINE uint32_t rotl32(uint32_t v, int s) { return __funnelshift_l(v, v, s); }

DINLINE void threefry2x32(uint32_t k0, uint32_t k1, uint32_t& x0, uint32_t& x1) {
    uint32_t k2 = k0 ^ k1 ^ 0x1BD11BDAu;
    x0 += k0; x1 += k1;
#define TF_R(r) { x0 += x1; x1 = rotl32(x1, r); x1 ^= x0; }
    TF_R(13) TF_R(15) TF_R(26) TF_R(6)
    x0 += k1; x1 += k2 + 1u;
    TF_R(17) TF_R(29) TF_R(16) TF_R(24)
    x0 += k2; x1 += k0 + 2u;
    TF_R(13) TF_R(15) TF_R(26) TF_R(6)
    x0 += k0; x1 += k1 + 3u;
    TF_R(17) TF_R(29) TF_R(16) TF_R(24)
    x0 += k1; x1 += k2 + 4u;
    TF_R(13) TF_R(15) TF_R(26) TF_R(6)
    x0 += k2; x1 += k0 + 5u;
#undef TF_R
}

DINLINE uint32_t smem_to_u32(const void* p) {
    uint32_t a;
    asm("{ .reg .u64 t; cvta.to.shared.u64 t, %1; cvt.u32.u64 %0, t; }"
        : "=r"(a) : "l"(p));
    return a;
}
DINLINE void ldm_x4(uint32_t* r, uint32_t addr) {
    asm volatile("ldmatrix.sync.aligned.m8n8.x4.shared.b16 {%0,%1,%2,%3}, [%4];"
                 : "=r"(r[0]), "=r"(r[1]), "=r"(r[2]), "=r"(r[3]) : "r"(addr));
}
DINLINE void mma_f16(float* c, const uint32_t* a, const uint32_t* b) {
    asm volatile(
        "mma.sync.aligned.m16n8k16.row.col.f32.f16.f16.f32 "
        "{%0,%1,%2,%3}, {%4,%5,%6,%7}, {%8,%9}, {%0,%1,%2,%3};"
        : "+f"(c[0]), "+f"(c[1]), "+f"(c[2]), "+f"(c[3])
        : "r"(a[0]), "r"(a[1]), "r"(a[2]), "r"(a[3]), "r"(b[0]), "r"(b[1]));
}
DINLINE void cp16(uint32_t dst, const void* src) {
    asm volatile("cp.async.cg.shared.global [%0], [%1], 16;" :: "r"(dst), "l"(src));
}
DINLINE void cp_commit() { asm volatile("cp.async.commit_group;"); }
template <int N> DINLINE void cp_wait() { asm volatile("cp.async.wait_group %0;" :: "n"(N)); }

DINLINE void split_fp16(float v, __half& h, __half& l) {
    h = __float2half_rn(v);
    l = __float2half_rn(v - __half2float(h));
}

// ---------------- prep kernels ----------------------------------------------
__global__ void pad_h_kernel(const float* __restrict__ x) {
    int c = threadIdx.x;
    int b = blockIdx.x;
    int pp = blockIdx.y;
    int py = pp / PADP, px = pp - py * PADP;
    float v = 0.f;
    int iy = py - 3, ix = px - 3;
    if (iy >= 0 && iy < 15 && ix >= 0 && ix < 15)
        v = x[((size_t)b * C_ + c) * HW_ + iy * 15 + ix];
    g_xph[((size_t)b * (PADP * PADP) + pp) * C_ + c] = __float2half_rn(v);
}

__global__ void wconv_kernel(const float* __restrict__ w, int taps, int tap_off) {
    int idx = blockIdx.x * 256 + threadIdx.x;
    if (idx >= C_ * C_ * taps) return;
    int tap = idx % taps;
    int rest = idx / taps;
    int ci = rest & 255;
    int co = rest >> 8;
    g_wh[((size_t)(tap_off + tap) * C_ + co) * C_ + ci] = __float2half_rn(w[idx]);
}

__global__ void wsplit1_kernel(const float* __restrict__ w,
                               __half* __restrict__ h, __half* __restrict__ l, int n) {
    int idx = blockIdx.x * 256 + threadIdx.x;
    if (idx >= n) return;
    split_fp16(w[idx], h[idx], l[idx]);
}

__global__ void lnT_kernel(const float* __restrict__ lnw, const float* __restrict__ lnb) {
    int p = blockIdx.x, c = threadIdx.x;
    g_lnwt[p * 256 + c] = lnw[c * 225 + p];
    g_lnbt[p * 256 + c] = lnb[c * 225 + p];
}

// ---------------- noise pre-generation (stream 2) ---------------------------
__global__ void __launch_bounds__(256)
noise_kernel(int step) {
    int b = blockIdx.x, yb = blockIdx.y, t = threadIdx.x;
    uint32_t fk0 = 0u, fk1 = (uint32_t)step;
    threefry2x32(0u, 42u, fk0, fk1);
    float* o = g_nz + (size_t)step * NELEM + (size_t)b * 57600;
#pragma unroll
    for (int e = 0; e < 15; e++) {
        int p = yb * 15 + e;
        uint32_t c0 = 0u, c1 = (uint32_t)((b * 256 + t) * 225 + p);
        threefry2x32(fk0, fk1, c0, c1);
        uint32_t bits = c0 ^ c1;
        o[p * 256 + t] = __uint_as_float(0x3f800000u | (bits >> 9)) - 1.0f;
    }
}

// ---------------- unified HMMA kernel ---------------------------------------
// CTA 128 px x 128 ch; 8 warps 2x4, warp 64x32. 3-stage cp.async, 1 sync/chunk.
// TERMS=1: acc = A*Bh.  TERMS=2: acc = A*Bh + A*Bl (B split fp16).
constexpr int EPI_CONV = 0, EPI_FUSION = 1, EPI_STEP = 2;
constexpr int RSTR = 40;                    // fp16 per row (80B)
constexpr int ARRB = 128 * RSTR * 2;        // 10240 B
constexpr int hsmem(int terms) { return 3 * (1 + terms) * ARRB; }

template <int KDIM, int EPI, bool GATHER, int TERMS>
__global__ void __launch_bounds__(256, 2)
hmma_kernel(const __half* __restrict__ A,
            const __half* __restrict__ BH, const __half* __restrict__ BL,
            const float* __restrict__ bs0, const float* __restrict__ bs1,
            const float* __restrict__ bs2, const float* __restrict__ bs3,
            __half* __restrict__ oh, float* __restrict__ of)
{
    constexpr int NARR = 1 + TERMS;
    constexpr int CHUNKB = NARR * ARRB;
    extern __shared__ __align__(16) char sm[];
    uint32_t smb = smem_to_u32(sm);

    int z = GATHER ? blockIdx.z : 0;
    int taps = GATHER ? c_taps[z] : 1;
    int kw = GATHER ? c_kw[z] : 1;
    int dil = GATHER ? c_dil[z] : 1;
    int off0 = GATHER ? (3 - c_pad[z]) : 0;
    int tap_off = GATHER ? c_tapoff[z] : 0;
    int co_off = GATHER ? c_cooff[z] : 0;
    int NCH = GATHER ? taps * 8 : KDIM / 32;
    const float* bias = (z == 0) ? bs0 : (z == 1) ? bs1 : (z == 2) ? bs2 : bs3;

    int t = threadIdx.x, lane = t & 31, wid = t >> 5;
    int wm = wid >> 2, wn = wid & 3;
    int row = t >> 1, q0 = (t & 1) * 2;
    int gp = blockIdx.x * 128 + row;
    int b = gp / 225, rem = gp - b * 225, y = rem / 15, xx = rem - y * 15;
    int coBase = blockIdx.y * 128;
    int bco = coBase + row;
    int sy0 = y + off0, sx0 = xx + off0;

    int ag = lane >> 3, alr = lane & 7;
    int a_row = (ag & 1) * 8 + alr, a_kb = (ag >> 1) * 16;
    int b_row = (ag >> 1) * 8 + alr, b_kb = (ag & 1) * 16;

    float acc[4][4][4];
#pragma unroll
    for (int i = 0; i < 4; i++)
#pragma unroll
        for (int j = 0; j < 4; j++)
#pragma unroll
            for (int k = 0; k < 4; k++) acc[i][j][k] = 0.f;

    auto stage = [&](int ch) {
        int tap = GATHER ? (ch >> 3) : 0;
        int ci0 = (GATHER ? (ch & 7) : ch) * 32;
        uint32_t base = smb + (uint32_t)(ch % 3) * CHUNKB;
        size_t asrc;
        if (GATHER) {
            int ky = tap / kw, kx = tap - ky * kw;
            asrc = (((size_t)b * PADP + (sy0 + ky * dil)) * PADP + (sx0 + kx * dil)) * C_ + ci0;
        } else {
            asrc = (size_t)gp * KDIM + ci0;
        }
        size_t bsrc = GATHER ? (((size_t)(tap_off + tap) * C_ + bco) * C_ + ci0)
                             : ((size_t)bco * KDIM + ci0);
        uint32_t drow = (uint32_t)row * (RSTR * 2);
#pragma unroll
        for (int s = 0; s < 2; s++) {
            int qq = q0 + s;
            uint32_t doff = drow + qq * 16;
            cp16(base + 0 * ARRB + doff, A + asrc + qq * 8);
            cp16(base + 1 * ARRB + doff, BH + bsrc + qq * 8);
            if (TERMS == 2) cp16(base + 2 * ARRB + doff, BL + bsrc + qq * 8);
        }
        cp_commit();
    };

    stage(0);
    stage(1);
#pragma unroll 1
    for (int ch = 0; ch < NCH; ch++) {
        cp_wait<1>();
        __syncthreads();
        uint32_t base = smb + (uint32_t)(ch % 3) * CHUNKB;
        uint32_t aH = base, bH = base + ARRB, bL = base + 2 * ARRB;
#pragma unroll
        for (int k16 = 0; k16 < 2; k16++) {
            uint32_t koff = k16 * 32;
            uint32_t bhf[8], blf[8];
#pragma unroll
            for (int h = 0; h < 2; h++) {
                int n0 = wn * 32 + h * 16;
                ldm_x4(&bhf[h * 4], bH + (uint32_t)((n0 + b_row) * (RSTR * 2)) + b_kb + koff);
                if (TERMS == 2)
                    ldm_x4(&blf[h * 4], bL + (uint32_t)((n0 + b_row) * (RSTR * 2)) + b_kb + koff);
            }
#pragma unroll
            for (int mt = 0; mt < 4; mt++) {
                int m0 = wm * 64 + mt * 16;
                uint32_t af[4];
                ldm_x4(af, aH + (uint32_t)((m0 + a_row) * (RSTR * 2)) + a_kb + koff);
#pragma unroll
                for (int nt = 0; nt < 4; nt++) {
                    mma_f16(acc[mt][nt], af, &bhf[nt * 2]);
                    if (TERMS == 2) mma_f16(acc[mt][nt], af, &blf[nt * 2]);
                }
            }
        }
        if (ch + 2 < NCH) stage(ch + 2);
        else cp_commit();
    }

    // epilogue
    float sst[2][2] = {{0.f, 0.f}, {0.f, 0.f}};
    int bstart = (blockIdx.x * 128) / 225;
#pragma unroll
    for (int mt = 0; mt < 4; mt++) {
#pragma unroll
        for (int nt = 0; nt < 4; nt++) {
            int co2 = wn * 32 + nt * 8 + (lane & 3) * 2;
            int co = coBase + co2;
            float bv0 = __ldg(bias + co), bv1 = __ldg(bias + co + 1);
#pragma unroll
            for (int rr = 0; rr < 2; rr++) {
                int pr = blockIdx.x * 128 + wm * 64 + mt * 16 + (lane >> 2) + rr * 8;
                float v0 = acc[mt][nt][rr * 2 + 0] + bv0;
                float v1 = acc[mt][nt][rr * 2 + 1] + bv1;
                if (EPI != EPI_STEP) { v0 = elu_f(v0); v1 = elu_f(v1); }
                if (EPI == EPI_CONV) {
                    size_t o = (size_t)pr * 1024 + co_off + co;
                    *reinterpret_cast<__half2*>(oh + o) = __floats2half2_rn(v0, v1);
                } else if (EPI == EPI_FUSION) {
                    size_t o = (size_t)pr * 256 + co;
                    *reinterpret_cast<float2*>(of + o) = {v0, v1};
                    *reinterpret_cast<__half2*>(oh + o) = __floats2half2_rn(v0, v1);
                } else {
                    size_t o = (size_t)pr * 256 + co;
                    *reinterpret_cast<float2*>(of + o) = {v0, v1};
                    int slot = pr / 225 - bstart;
                    sst[slot][0] += v0 + v1;
                    sst[slot][1] += v0 * v0 + v1 * v1;
                }
            }
        }
    }

    if (EPI == EPI_STEP) {
        __syncthreads();
        float* red = reinterpret_cast<float*>(sm);
        red[t * 4 + 0] = sst[0][0];
        red[t * 4 + 1] = sst[0][1];
        red[t * 4 + 2] = sst[1][0];
        red[t * 4 + 3] = sst[1][1];
        __syncthreads();
        for (int o2 = 128; o2 > 0; o2 >>= 1) {
            if (t < o2) {
#pragma unroll
                for (int k = 0; k < 4; k++) red[t * 4 + k] += red[(t + o2) * 4 + k];
            }
            __syncthreads();
        }
        if (t == 0) {
            int cta = blockIdx.y * MTILES + blockIdx.x;
#pragma unroll
            for (int k = 0; k < 4; k++) g_stats3[cta * 4 + k] = red[k];
        }
    }
}

// ---------------- per-step update (mu/rs derived inline; noise precomputed) --
__global__ void __launch_bounds__(256)
step_update_kernel(const float* __restrict__ ybuf,
                   float* __restrict__ xc,
                   __half* __restrict__ xch,
                   float* __restrict__ dout,
                   const float* __restrict__ sp_arr,
                   const float* __restrict__ ss_arr,
                   const float* __restrict__ rw_arr,
                   const float* __restrict__ prob_arr,
                   int step, int last)
{
    int b = blockIdx.x;
    int t = threadIdx.x;

    // combine y-stat partials for this batch (deterministic, identical per block)
    double s1d = 0.0, s2d = 0.0;
    int cxlo = (225 * b) >> 7;
    int cxhi = (225 * b + 224) >> 7;
    for (int cx = cxlo; cx <= cxhi; cx++) {
        int bstart = (cx * 128) / 225;
        int slot = b - bstart;
        if (slot >= 0 && slot < 2) {
            for (int cy = 0; cy < 2; cy++) {
                s1d += (double)g_stats3[(cy * MTILES + cx) * 4 + slot * 2 + 0];
                s2d += (double)g_stats3[(cy * MTILES + cx) * 4 + slot * 2 + 1];
            }
        }
    }
    const double n = (double)(C_ * HW_);
    double mu_d = s1d / n;
    double var_d = s2d / n - mu_d * mu_d;
    float mu = (float)mu_d;
    float rs = (float)(1.0 / sqrt(var_d + 1e-5));

    float sp = sp_arr[step];
    float cns = prob_arr[step] * ss_arr[step];
    float rw1 = 1.f + rw_arr[step];

    size_t bbase = (size_t)b * 57600;
    const float* nz = g_nz + (size_t)step * NELEM + bbase;

    float s1 = 0.f, s2 = 0.f;
#pragma unroll
    for (int e = 0; e < 15; e++) {
        int p = blockIdx.y * 15 + e;
        int j = p * 256 + t;
        float yv = ybuf[bbase + j];
        float d = (yv - mu) * rs;
        d = fmaf(d, g_lnwt[j], g_lnbt[j]);
        d = elu_f(d);
        s1 += d; s2 = fmaf(d, d, s2);
        float u = nz[j];
        float xn = fmaf(xc[bbase + j], rw1, fmaf(d, sp, u * cns));
        if (last) {
            dout[((size_t)b * 256 + t) * 225 + p] = xn;
        } else {
            xc[bbase + j] = xn;
            xch[bbase + j] = __float2half_rn(xn);
        }
    }

    __shared__ float red[256];
    red[t] = s1; __syncthreads();
    for (int off = 128; off > 0; off >>= 1) {
        if (t < off) red[t] += red[t + off];
        __syncthreads();
    }
    size_t sbase = ((size_t)step * B_ + b) * UPD_BLOCKS;
    if (t == 0) g_stats2[(sbase + blockIdx.y) * 2 + 0] = red[0];
    __syncthreads();
    red[t] = s2; __syncthreads();
    for (int off = 128; off > 0; off >>= 1) {
        if (t < off) red[t] += red[t + off];
        __syncthreads();
    }
    if (t == 0) g_stats2[(sbase + blockIdx.y) * 2 + 1] = red[0];
}

// ---------------- all-steps unbiased variance (single launch at end) --------
__global__ void var_final_kernel(float* __restrict__ out_var) {
    int step = blockIdx.x;
    int b = threadIdx.x;
    double s1 = 0.0, s2 = 0.0;
    size_t sbase = ((size_t)step * B_ + b) * UPD_BLOCKS;
    for (int k = 0; k < UPD_BLOCKS; k++) {
        s1 += (double)g_stats2[(sbase + k) * 2 + 0];
        s2 += (double)g_stats2[(sbase + k) * 2 + 1];
    }
    const double n = (double)(C_ * HW_);
    double v = (s2 - s1 * s1 / n) / (n - 1.0);
    out_var[b * S_ + step] = (float)v;
}

// ---------------- launch ----------------------------------------------------
extern "C" void kernel_launch(void* const* d_in, const int* in_sizes, int n_in,
                              void* d_out, int out_size) {
    const float* x    = (const float*)d_in[0];
    const float* prob = (const float*)d_in[1];
    const float* w3   = (const float*)d_in[2];
    const float* b3   = (const float*)d_in[3];
    const float* w3d  = (const float*)d_in[4];
    const float* b3d  = (const float*)d_in[5];
    const float* w5   = (const float*)d_in[6];
    const float* b5   = (const float*)d_in[7];
    const float* w7   = (const float*)d_in[8];
    const float* b7   = (const float*)d_in[9];
    const float* wf   = (const float*)d_in[10];
    const float* bf   = (const float*)d_in[11];
    const float* w1   = (const float*)d_in[12];
    const float* b1   = (const float*)d_in[13];
    const float* lnw  = (const float*)d_in[14];
    const float* lnb  = (const float*)d_in[15];
    const float* spar = (const float*)d_in[16];
    const float* ssc  = (const float*)d_in[17];
    const float* rwv  = (const float*)d_in[18];

    float* out = (float*)d_out;
    float* out_var = out + (size_t)NELEM;

    __half *xph, *wh, *wfh, *wfl, *w1h, *w1l, *cath, *xch;
    float *xc, *ybuf;
    cudaGetSymbolAddress((void**)&xph, g_xph);
    cudaGetSymbolAddress((void**)&wh, g_wh);
    cudaGetSymbolAddress((void**)&wfh, g_wfh);
    cudaGetSymbolAddress((void**)&wfl, g_wfl);
    cudaGetSymbolAddress((void**)&w1h, g_w1h);
    cudaGetSymbolAddress((void**)&w1l, g_w1l);
    cudaGetSymbolAddress((void**)&cath, g_cath);
    cudaGetSymbolAddress((void**)&xch, g_xch);
    cudaGetSymbolAddress((void**)&xc, g_xc);
    cudaGetSymbolAddress((void**)&ybuf, g_ybuf);

    static cudaStream_t s2 = nullptr;
    static cudaEvent_t evF;
    static cudaEvent_t evN[S_];
    if (!s2) {
        cudaStreamCreate(&s2);
        cudaEventCreateWithFlags(&evF, cudaEventDisableTiming);
        for (int i = 0; i < S_; i++) cudaEventCreateWithFlags(&evN[i], cudaEventDisableTiming);
    }

    cudaFuncSetAttribute(hmma_kernel<256, EPI_CONV, true, 1>,
                         cudaFuncAttributeMaxDynamicSharedMemorySize, hsmem(1));
    cudaFuncSetAttribute(hmma_kernel<1024, EPI_FUSION, false, 2>,
                         cudaFuncAttributeMaxDynamicSharedMemorySize, hsmem(2));
    cudaFuncSetAttribute(hmma_kernel<256, EPI_STEP, false, 2>,
                         cudaFuncAttributeMaxDynamicSharedMemorySize, hsmem(2));

    // fork: noise generation for all 8 steps on stream 2
    cudaEventRecord(evF, 0);
    cudaStreamWaitEvent(s2, evF, 0);
    for (int s = 0; s < S_; s++) {
        noise_kernel<<<dim3(B_, 15), 256, 0, s2>>>(s);
        cudaEventRecord(evN[s], s2);
    }

    // prep
    pad_h_kernel<<<dim3(B_, PADP * PADP), 256>>>(x);
    wconv_kernel<<<(C_ * C_ * 9 + 255) / 256, 256>>>(w3, 9, 0);
    wconv_kernel<<<(C_ * C_ * 9 + 255) / 256, 256>>>(w3d, 9, 9);
    wconv_kernel<<<(C_ * C_ * 25 + 255) / 256, 256>>>(w5, 25, 18);
    wconv_kernel<<<(C_ * C_ * 49 + 255) / 256, 256>>>(w7, 49, 43);
    wsplit1_kernel<<<(4 * C_ * C_ + 255) / 256, 256>>>(wf, wfh, wfl, 4 * C_ * C_);
    wsplit1_kernel<<<(C_ * C_ + 255) / 256, 256>>>(w1, w1h, w1l, C_ * C_);
    lnT_kernel<<<HW_, 256>>>(lnw, lnb);

    // all 4 multi-scale convs in ONE launch (z = conv id) -> cat (fp16)
    hmma_kernel<256, EPI_CONV, true, 1><<<dim3(MTILES, 2, 4), 256, hsmem(1)>>>(
        xph, wh, nullptr, b3, b3d, b5, b7, cath, nullptr);

    // fusion GEMM (K=1024) -> xc fp32 + xch fp16
    hmma_kernel<1024, EPI_FUSION, false, 2><<<dim3(MTILES, 2), 256, hsmem(2)>>>(
        cath, wfh, wfl, bf, bf, bf, bf, xch, xc);

    // 8 NCA steps: GEMM(+y-stat partials) -> update
    for (int i = 0; i < S_; i++) {
        hmma_kernel<256, EPI_STEP, false, 2><<<dim3(MTILES, 2), 256, hsmem(2)>>>(
            xch, w1h, w1l, b1, b1, b1, b1, nullptr, ybuf);
        cudaStreamWaitEvent(0, evN[i], 0);
        step_update_kernel<<<dim3(B_, UPD_BLOCKS), 256>>>(
            ybuf, xc, xch, out, spar, ssc, rwv, prob, i, i == S_ - 1);
    }
    var_final_kernel<<<S_, 256>>>(out_var);
}